// round 11
// baseline (speedup 1.0000x reference)
#include <cuda_runtime.h>
#include <cuda_bf16.h>
#include <math.h>
#include <stdint.h>

#define D_MODEL 2048
#define SEQ     2048
#define BATCH   2
#define ROWS    (BATCH*SEQ)     /* 4096 */
#define D_FF    5504
#define NH      16
#define DK      128

/* ================= scratch ================= */
__device__ float g_v  [(size_t)ROWS*D_MODEL];
__device__ float g_res[(size_t)ROWS*D_MODEL];

__device__ __nv_bfloat16 g_xnh[(size_t)ROWS*D_MODEL];
__device__ __nv_bfloat16 g_xnl[(size_t)ROWS*D_MODEL];
__device__ __nv_bfloat16 g_ath[(size_t)ROWS*D_MODEL];
__device__ __nv_bfloat16 g_atl[(size_t)ROWS*D_MODEL];
__device__ __nv_bfloat16 g_f1h[(size_t)ROWS*D_FF];
__device__ __nv_bfloat16 g_f1l[(size_t)ROWS*D_FF];
__device__ __nv_bfloat16 g_qh [(size_t)ROWS*D_MODEL];
__device__ __nv_bfloat16 g_ql [(size_t)ROWS*D_MODEL];
__device__ __nv_bfloat16 g_kh [(size_t)ROWS*D_MODEL];
__device__ __nv_bfloat16 g_kl [(size_t)ROWS*D_MODEL];
__device__ __nv_bfloat16 g_vth[(size_t)BATCH*NH*DK*SEQ];
__device__ __nv_bfloat16 g_vtl[(size_t)BATCH*NH*DK*SEQ];

__device__ __nv_bfloat16 g_wqkvh[(size_t)3*D_MODEL*D_MODEL];
__device__ __nv_bfloat16 g_wqkvl[(size_t)3*D_MODEL*D_MODEL];
__device__ __nv_bfloat16 g_woh  [(size_t)D_MODEL*D_MODEL];
__device__ __nv_bfloat16 g_wol  [(size_t)D_MODEL*D_MODEL];
__device__ __nv_bfloat16 g_w13h [(size_t)2*D_FF*D_MODEL];
__device__ __nv_bfloat16 g_w13l [(size_t)2*D_FF*D_MODEL];
__device__ __nv_bfloat16 g_w2h  [(size_t)D_MODEL*D_FF];
__device__ __nv_bfloat16 g_w2l  [(size_t)D_MODEL*D_FF];

/* ================= helpers ================= */
__device__ __forceinline__ uint32_t smem_u32(const void* p) {
    uint32_t a;
    asm("{ .reg .u64 t; cvta.to.shared.u64 t, %1; cvt.u32.u64 %0, t; }"
        : "=r"(a) : "l"(p));
    return a;
}

#define LDSM_X4(r0,r1,r2,r3, addr) \
    asm volatile("ldmatrix.sync.aligned.m8n8.x4.shared.b16 {%0,%1,%2,%3}, [%4];" \
        : "=r"(r0),"=r"(r1),"=r"(r2),"=r"(r3) : "r"(addr))

#define MMA16816(d, a0,a1,a2,a3, b0,b1) \
    asm volatile("mma.sync.aligned.m16n8k16.row.col.f32.bf16.bf16.f32 " \
        "{%0,%1,%2,%3}, {%4,%5,%6,%7}, {%8,%9}, {%0,%1,%2,%3};" \
        : "+f"((d)[0]),"+f"((d)[1]),"+f"((d)[2]),"+f"((d)[3]) \
        : "r"(a0),"r"(a1),"r"(a2),"r"(a3), "r"(b0),"r"(b1))

__device__ __forceinline__ void split_pack2(float x, float y,
                                            uint32_t& h, uint32_t& l) {
    __nv_bfloat16 hx = __float2bfloat16(x), hy = __float2bfloat16(y);
    __nv_bfloat162 hv(hx, hy);
    __nv_bfloat162 lv(__float2bfloat16(x - __bfloat162float(hx)),
                      __float2bfloat16(y - __bfloat162float(hy)));
    h = *reinterpret_cast<uint32_t*>(&hv);
    l = *reinterpret_cast<uint32_t*>(&lv);
}

__device__ __forceinline__ void split_store2(__nv_bfloat16* H, __nv_bfloat16* L,
                                             size_t idx, float x, float y) {
    __nv_bfloat16 hx = __float2bfloat16(x), hy = __float2bfloat16(y);
    __nv_bfloat16 lx = __float2bfloat16(x - __bfloat162float(hx));
    __nv_bfloat16 ly = __float2bfloat16(y - __bfloat162float(hy));
    *reinterpret_cast<__nv_bfloat162*>(H + idx) = __nv_bfloat162(hx, hy);
    *reinterpret_cast<__nv_bfloat162*>(L + idx) = __nv_bfloat162(lx, ly);
}

/* ================= mega weight split ================= */
__global__ __launch_bounds__(256) void megasplit_kernel(
    const float* __restrict__ Wq, const float* __restrict__ Wk,
    const float* __restrict__ Wv, const float* __restrict__ Wo,
    const float* __restrict__ W1, const float* __restrict__ W3,
    const float* __restrict__ W2,
    __nv_bfloat16* qkvH, __nv_bfloat16* qkvL,
    __nv_bfloat16* woH,  __nv_bfloat16* woL,
    __nv_bfloat16* w13H, __nv_bfloat16* w13L,
    __nv_bfloat16* w2H,  __nv_bfloat16* w2L)
{
    const size_t S1 = (size_t)D_MODEL*D_MODEL/4;
    const size_t S2 = (size_t)D_FF*D_MODEL/4;
    size_t i4 = (size_t)blockIdx.x*256 + threadIdx.x;
    if (i4 >= 4*S1 + 3*S2) return;

    float4 v; __nv_bfloat16 *H, *L; size_t d4;
    if (i4 < 3*S1) {
        size_t seg = i4 / S1, off = i4 - seg*S1;
        const float* W = (seg == 0) ? Wq : (seg == 1) ? Wk : Wv;
        v = ((const float4*)W)[off];
        H = qkvH; L = qkvL; d4 = i4;
    } else if (i4 < 4*S1) {
        size_t off = i4 - 3*S1;
        v = ((const float4*)Wo)[off];
        H = woH; L = woL; d4 = off;
    } else if (i4 < 4*S1 + 2*S2) {
        size_t off = i4 - 4*S1;
        int isW3 = off >= S2; if (isW3) off -= S2;
        v = ((const float4*)(isW3 ? W3 : W1))[off];
        size_t r = off >> 9, c = off & 511;
        size_t d = (r >> 6)*128 + (isW3 ? 64 : 0) + (r & 63);
        H = w13H; L = w13L; d4 = d*512 + c;
    } else {
        size_t off = i4 - 4*S1 - 2*S2;
        v = ((const float4*)W2)[off];
        H = w2H; L = w2L; d4 = off;
    }
    split_store2(H, L, d4*4,   v.x, v.y);
    split_store2(H, L, d4*4+2, v.z, v.w);
}

/* ================= RMSNorm (+split) ================= */
__global__ __launch_bounds__(256) void rmsnorm_split_kernel(
    const float* __restrict__ X, const float* __restrict__ g,
    __nv_bfloat16* __restrict__ H, __nv_bfloat16* __restrict__ L)
{
    const int row = blockIdx.x;
    const float* x = X + (size_t)row * D_MODEL;

    float ss = 0.f;
    #pragma unroll
    for (int i = threadIdx.x; i < D_MODEL/4; i += 256) {
        float4 v = ((const float4*)x)[i];
        ss += v.x*v.x + v.y*v.y + v.z*v.z + v.w*v.w;
    }
    #pragma unroll
    for (int off = 16; off; off >>= 1)
        ss += __shfl_xor_sync(0xffffffffu, ss, off);
    __shared__ float red[8];
    if ((threadIdx.x & 31) == 0) red[threadIdx.x >> 5] = ss;
    __syncthreads();
    float tot = red[0]+red[1]+red[2]+red[3]+red[4]+red[5]+red[6]+red[7];
    float rinv = rsqrtf(tot * (1.0f / D_MODEL) + 1e-5f);

    #pragma unroll
    for (int i = threadIdx.x; i < D_MODEL/4; i += 256) {
        float4 v = ((const float4*)x)[i];
        float4 gg = ((const float4*)g)[i];
        size_t base = (size_t)row * D_MODEL + i*4;
        split_store2(H, L, base,   v.x*rinv*gg.x, v.y*rinv*gg.y);
        split_store2(H, L, base+2, v.z*rinv*gg.z, v.w*rinv*gg.w);
    }
}

/* ================= bf16x3 HMMA GEMM, 256x128 CTA tile =================
   8 warps in 4x2; each warp 64 rows x 64 cols (4 mf x 8 nf frags).
   MODE 0: C = A B^T (+R); MODE 1: QKV+RoPE+split; MODE 2: W13+SwiGLU. */
#define CHUNK_K     64
#define A_TILE_B    (256*128)              /* 32KB */
#define B_TILE_B    (128*128)              /* 16KB */
#define STAGE_BYTES (2*A_TILE_B + 2*B_TILE_B)   /* 96KB */
#define GSTAGES     2
#define GEMM_SMEM   (GSTAGES*STAGE_BYTES)  /* 192KB */

template<int MODE>
__global__ __launch_bounds__(256, 1) void gemm_kernel(
    const __nv_bfloat16* __restrict__ Ah, const __nv_bfloat16* __restrict__ Al,
    const __nv_bfloat16* __restrict__ Bh, const __nv_bfloat16* __restrict__ Bl,
    float* __restrict__ C, const float* __restrict__ R,
    __nv_bfloat16* __restrict__ OH, __nv_bfloat16* __restrict__ OL,
    __nv_bfloat16* __restrict__ KH2, __nv_bfloat16* __restrict__ KL2,
    int M, int N, int K)
{
    extern __shared__ char smem[];
    const uint32_t sb = smem_u32(smem);
    const int tid = threadIdx.x;
    const int wid = tid >> 5, lane = tid & 31;
    const int wr = wid & 3;            /* 4 row groups of 64 */
    const int wc = wid >> 2;           /* 2 col groups of 64 */
    const int NC = K / CHUNK_K;

    const int rowA = blockIdx.y * 256;
    const int rowB = blockIdx.x * 128;

    const __nv_bfloat16* srcA_h = Ah + (size_t)rowA * K;
    const __nv_bfloat16* srcA_l = Al + (size_t)rowA * K;
    const __nv_bfloat16* srcB_h = Bh + (size_t)rowB * K;
    const __nv_bfloat16* srcB_l = Bl + (size_t)rowB * K;

    const int r0 = tid >> 3;           /* 0..31 */
    const int u  = tid & 7;            /* 16B unit */

    #define LOAD_STAGE(chunk, s) do {                                        \
        uint32_t _stb = sb + (s) * STAGE_BYTES;                              \
        size_t _k0 = (size_t)(chunk) * CHUNK_K;                              \
        _Pragma("unroll")                                                    \
        for (int _i = 0; _i < 8; _i++) {                                     \
            int _r = r0 + _i * 32;                                           \
            uint32_t _d = _r * 128 + ((u ^ (_r & 7)) * 16);                  \
            const void* _g1 = srcA_h + (size_t)_r * K + _k0 + u * 8;         \
            const void* _g2 = srcA_l + (size_t)_r * K + _k0 + u * 8;         \
            asm volatile("cp.async.cg.shared.global [%0], [%1], 16;"         \
                         :: "r"(_stb + _d), "l"(_g1));                       \
            asm volatile("cp.async.cg.shared.global [%0], [%1], 16;"         \
                         :: "r"(_stb + 32768 + _d), "l"(_g2));               \
        }                                                                    \
        _Pragma("unroll")                                                    \
        for (int _i = 0; _i < 4; _i++) {                                     \
            int _r = r0 + _i * 32;                                           \
            uint32_t _d = _r * 128 + ((u ^ (_r & 7)) * 16);                  \
            const void* _g1 = srcB_h + (size_t)_r * K + _k0 + u * 8;         \
            const void* _g2 = srcB_l + (size_t)_r * K + _k0 + u * 8;         \
            asm volatile("cp.async.cg.shared.global [%0], [%1], 16;"         \
                         :: "r"(_stb + 65536 + _d), "l"(_g1));               \
            asm volatile("cp.async.cg.shared.global [%0], [%1], 16;"         \
                         :: "r"(_stb + 81920 + _d), "l"(_g2));               \
        }                                                                    \
        asm volatile("cp.async.commit_group;" ::: "memory");                 \
    } while (0)

    LOAD_STAGE(0, 0);
    if (NC > 1) LOAD_STAGE(1, 1);

    float acc[4][8][4];
    #pragma unroll
    for (int i = 0; i < 4; i++)
        #pragma unroll
        for (int j = 0; j < 8; j++)
            #pragma unroll
            for (int c = 0; c < 4; c++) acc[i][j][c] = 0.f;

    const int lrow = lane & 15;
    const int lu   = lane >> 4;

    for (int j = 0; j < NC; j++) {
        if (j + 1 < NC) asm volatile("cp.async.wait_group 1;" ::: "memory");
        else            asm volatile("cp.async.wait_group 0;" ::: "memory");
        __syncthreads();

        const uint32_t stb = sb + (j & 1) * STAGE_BYTES;
        const uint32_t tAh = stb;
        const uint32_t tAl = stb + 32768;
        const uint32_t tBh = stb + 65536;
        const uint32_t tBl = stb + 81920;

        #pragma unroll
        for (int ks = 0; ks < 4; ks++) {
            const int unit = ks*2 + lu;
            uint32_t ah[4][4], al[4][4];
            #pragma unroll
            for (int mf = 0; mf < 4; mf++) {
                const int row = wr*64 + mf*16 + lrow;
                const uint32_t off = row*128 + ((unit ^ (row & 7)) << 4);
                LDSM_X4(ah[mf][0], ah[mf][1], ah[mf][2], ah[mf][3], tAh + off);
                LDSM_X4(al[mf][0], al[mf][1], al[mf][2], al[mf][3], tAl + off);
            }
            #pragma unroll
            for (int nf2 = 0; nf2 < 4; nf2++) {
                const int brow = wc*64 + nf2*16 + lrow;
                const uint32_t off = brow*128 + ((unit ^ (brow & 7)) << 4);
                uint32_t bh0,bh1,bh2,bh3, bl0,bl1,bl2,bl3;
                LDSM_X4(bh0,bh1,bh2,bh3, tBh + off);
                LDSM_X4(bl0,bl1,bl2,bl3, tBl + off);
                #pragma unroll
                for (int mf = 0; mf < 4; mf++) {
                    MMA16816(acc[mf][nf2*2+0], ah[mf][0],ah[mf][1],ah[mf][2],ah[mf][3], bh0, bh2);
                    MMA16816(acc[mf][nf2*2+0], ah[mf][0],ah[mf][1],ah[mf][2],ah[mf][3], bl0, bl2);
                    MMA16816(acc[mf][nf2*2+0], al[mf][0],al[mf][1],al[mf][2],al[mf][3], bh0, bh2);
                    MMA16816(acc[mf][nf2*2+1], ah[mf][0],ah[mf][1],ah[mf][2],ah[mf][3], bh1, bh3);
                    MMA16816(acc[mf][nf2*2+1], ah[mf][0],ah[mf][1],ah[mf][2],ah[mf][3], bl1, bl3);
                    MMA16816(acc[mf][nf2*2+1], al[mf][0],al[mf][1],al[mf][2],al[mf][3], bh1, bh3);
                }
            }
        }
        __syncthreads();
        if (j + GSTAGES < NC) LOAD_STAGE(j + GSTAGES, j & 1);
    }

    const int erowL = wr*64 + (lane >> 2);        /* local row base */
    const int ecolL = wc*64 + (lane & 3)*2;       /* local col base */

    if (MODE == 0) {
        const int erow = rowA + erowL;
        const int ecol = rowB + ecolL;
        #pragma unroll
        for (int mf = 0; mf < 4; mf++) {
            #pragma unroll
            for (int half = 0; half < 2; half++) {
                const int row = erow + mf*16 + half*8;
                float* crow = C + (size_t)row * N + ecol;
                const float* rrow = R ? (R + (size_t)row * N + ecol) : (const float*)0;
                #pragma unroll
                for (int nf = 0; nf < 8; nf++) {
                    float2 v = make_float2(acc[mf][nf][half*2+0], acc[mf][nf][half*2+1]);
                    if (rrow) {
                        float2 rv = *(const float2*)(rrow + nf*8);
                        v.x += rv.x; v.y += rv.y;
                    }
                    *(float2*)(crow + nf*8) = v;
                }
            }
        }
    } else if (MODE == 1) {
        const int seg = blockIdx.x >> 4;
        const int colT0 = ((blockIdx.x & 15) << 7) + ecolL;
        const float QSC = 0.08838834764831845f * 1.4426950408889634f;
        #pragma unroll
        for (int mf = 0; mf < 4; mf++) {
            #pragma unroll
            for (int half = 0; half < 2; half++) {
                const int rowg = rowA + erowL + mf*16 + half*8;
                const int s = rowg & (SEQ-1);
                #pragma unroll
                for (int nf = 0; nf < 8; nf++) {
                    const int col = colT0 + nf*8;
                    float v0 = acc[mf][nf][half*2+0];
                    float v1 = acc[mf][nf][half*2+1];
                    if (seg == 2) {
                        *(float2*)(C + (size_t)rowg*D_MODEL + col) = make_float2(v0, v1);
                    } else {
                        const int kidx = (col & 127) >> 1;
                        const float freq = expf(-0.14391156831212824f * (float)kidx);
                        float sn, cs;
                        sincosf((float)s * freq, &sn, &cs);
                        float e = v0*cs - v1*sn;
                        float o = v0*sn + v1*cs;
                        if (seg == 0) {
                            split_store2(OH, OL, (size_t)rowg*D_MODEL + col,
                                         e*QSC, o*QSC);
                        } else {
                            split_store2(KH2, KL2, (size_t)rowg*D_MODEL + col, e, o);
                        }
                    }
                }
            }
        }
    } else {
        /* MODE 2: wc=0 warps own f1 (cols 0..63), wc=1 own f3 (cols 64..127)
           of the same global 64-col range. Exchange f3 via smem. */
        float* sx = (float*)smem;              /* [256][68] fp32 = 69.6KB */
        __syncthreads();
        if (wc == 1) {
            #pragma unroll
            for (int mf = 0; mf < 4; mf++) {
                #pragma unroll
                for (int half = 0; half < 2; half++) {
                    const int rl = erowL + mf*16 + half*8;
                    #pragma unroll
                    for (int nf = 0; nf < 8; nf++) {
                        const int jj = (ecolL - 64) + nf*8;
                        sx[rl*68 + jj]     = acc[mf][nf][half*2+0];
                        sx[rl*68 + jj + 1] = acc[mf][nf][half*2+1];
                    }
                }
            }
        }
        __syncthreads();
        if (wc == 0) {
            #pragma unroll
            for (int mf = 0; mf < 4; mf++) {
                #pragma unroll
                for (int half = 0; half < 2; half++) {
                    const int rl = erowL + mf*16 + half*8;
                    const size_t rowg = (size_t)(rowA + rl);
                    #pragma unroll
                    for (int nf = 0; nf < 8; nf++) {
                        const int jj = ecolL + nf*8;
                        float a0 = acc[mf][nf][half*2+0];
                        float a1 = acc[mf][nf][half*2+1];
                        float b0 = sx[rl*68 + jj];
                        float b1 = sx[rl*68 + jj + 1];
                        float h0 = a0 / (1.f + expf(-a0)) * b0;
                        float h1 = a1 / (1.f + expf(-a1)) * b1;
                        split_store2(OH, OL,
                                     rowg*D_FF + (size_t)blockIdx.x*64 + jj,
                                     h0, h1);
                    }
                }
            }
        }
    }
    #undef LOAD_STAGE
}

/* ================= V transpose + split ================= */
__global__ __launch_bounds__(256) void vtrans_split_kernel(
    const float* __restrict__ V, __nv_bfloat16* __restrict__ H,
    __nv_bfloat16* __restrict__ L)
{
    __shared__ float t[32][33];
    const int s0 = blockIdx.x * 32, d0 = blockIdx.y * 32, bh = blockIdx.z;
    const int b = bh >> 4, h = bh & 15;
    const int tx = threadIdx.x & 31, ty = threadIdx.x >> 5;
    #pragma unroll
    for (int j = 0; j < 4; j++) {
        int s = s0 + ty + j*8;
        t[ty + j*8][tx] = V[((size_t)(b*SEQ + s))*D_MODEL + h*DK + d0 + tx];
    }
    __syncthreads();
    #pragma unroll
    for (int j = 0; j < 4; j++) {
        int d = d0 + ty + j*8;
        float val = t[tx][ty + j*8];
        __nv_bfloat16 hi = __float2bfloat16(val);
        __nv_bfloat16 lo = __float2bfloat16(val - __bfloat162float(hi));
        size_t idx = ((size_t)bh*DK + d)*SEQ + s0 + tx;
        H[idx] = hi; L[idx] = lo;
    }
}

/* ================= HMMA causal flash attention (bf16x3) ================= */
#define ATTN_SMEM  (192*1024)

__global__ __launch_bounds__(256, 1) void attn_hmma_kernel(
    const __nv_bfloat16* __restrict__ Qh, const __nv_bfloat16* __restrict__ Ql,
    const __nv_bfloat16* __restrict__ Kh, const __nv_bfloat16* __restrict__ Kl,
    const __nv_bfloat16* __restrict__ Vh, const __nv_bfloat16* __restrict__ Vl,
    __nv_bfloat16* __restrict__ Oh, __nv_bfloat16* __restrict__ Ol)
{
    extern __shared__ char smem[];
    const uint32_t sb  = smem_u32(smem);
    const uint32_t sQh = sb, sQl = sb + 32768;
    const int qb = (int)gridDim.x - 1 - (int)blockIdx.x;
    const int bh = blockIdx.y;
    const int b = bh >> 4, h = bh & 15;
    const int tid = threadIdx.x, wid = tid >> 5, lane = tid & 31;
    const int r0 = lane >> 2, qd = lane & 3, lrow = lane & 15, lu = lane >> 4;

    const size_t qrow0 = (size_t)b*SEQ + (size_t)qb*128;
    const size_t krow0 = (size_t)b*SEQ;
    const int hoff = h*DK;
    const size_t vbase = (size_t)bh*DK*SEQ;
    const int NKB = 2*qb + 2;

    #pragma unroll
    for (int it = 0; it < 8; it++) {
        int lin = it*256 + tid;
        int r = lin >> 4, un = lin & 15;
        uint32_t dsw = r*256 + ((un>>3)<<7) + (((un&7) ^ (r&7)) << 4);
        const void* gh = Qh + (qrow0 + r)*D_MODEL + hoff + un*8;
        const void* gl = Ql + (qrow0 + r)*D_MODEL + hoff + un*8;
        asm volatile("cp.async.cg.shared.global [%0], [%1], 16;" :: "r"(sQh+dsw), "l"(gh));
        asm volatile("cp.async.cg.shared.global [%0], [%1], 16;" :: "r"(sQl+dsw), "l"(gl));
    }

    #define LOAD_KV(kb_, s_) do {                                                  \
        uint32_t _st = sb + 65536 + (uint32_t)(s_)*65536;                          \
        size_t _kr = krow0 + (size_t)(kb_)*64;                                     \
        _Pragma("unroll")                                                          \
        for (int _it = 0; _it < 4; _it++) {                                        \
            int _lin = _it*256 + tid;                                              \
            int _r = _lin >> 4, _un = _lin & 15;                                   \
            uint32_t _d = _r*256 + ((_un>>3)<<7) + (((_un&7) ^ (_r&7)) << 4);      \
            const void* _g1 = Kh + (_kr + _r)*D_MODEL + hoff + _un*8;              \
            const void* _g2 = Kl + (_kr + _r)*D_MODEL + hoff + _un*8;              \
            asm volatile("cp.async.cg.shared.global [%0], [%1], 16;"               \
                         :: "r"(_st+_d), "l"(_g1));                                \
            asm volatile("cp.async.cg.shared.global [%0], [%1], 16;"               \
                         :: "r"(_st+16384+_d), "l"(_g2));                          \
        }                                                                          \
        _Pragma("unroll")                                                          \
        for (int _it = 0; _it < 4; _it++) {                                        \
            int _lin = _it*256 + tid;                                              \
            int _r = _lin >> 3, _u = _lin & 7;                                     \
            uint32_t _d = _r*128 + ((_u ^ (_r&7)) << 4);                           \
            const void* _g1 = Vh + vbase + (size_t)_r*SEQ + (size_t)(kb_)*64 + _u*8; \
            const void* _g2 = Vl + vbase + (size_t)_r*SEQ + (size_t)(kb_)*64 + _u*8; \
            asm volatile("cp.async.cg.shared.global [%0], [%1], 16;"               \
                         :: "r"(_st+32768+_d), "l"(_g1));                          \
            asm volatile("cp.async.cg.shared.global [%0], [%1], 16;"               \
                         :: "r"(_st+49152+_d), "l"(_g2));                          \
        }                                                                          \
        asm volatile("cp.async.commit_group;" ::: "memory");                       \
    } while (0)

    LOAD_KV(0, 0);
    LOAD_KV(1, 1);

    float m0 = -1e30f, m1 = -1e30f, l0 = 0.f, l1 = 0.f;
    float oacc[16][4];
    #pragma unroll
    for (int i = 0; i < 16; i++)
        #pragma unroll
        for (int c = 0; c < 4; c++) oacc[i][c] = 0.f;

    for (int kb = 0; kb < NKB; kb++) {
        if (kb + 1 < NKB) asm volatile("cp.async.wait_group 1;" ::: "memory");
        else              asm volatile("cp.async.wait_group 0;" ::: "memory");
        __syncthreads();
        const uint32_t st = sb + 65536 + (uint32_t)(kb & 1)*65536;

        float sacc[8][4];
        #pragma unroll
        for (int i = 0; i < 8; i++)
            #pragma unroll
            for (int c = 0; c < 4; c++) sacc[i][c] = 0.f;

        #pragma unroll
        for (int kk = 0; kk < 8; kk++) {
            const int un = kk*2 + lu;
            const int arow = wid*16 + lrow;
            const uint32_t aoff = arow*256 + ((un>>3)<<7) + (((un&7) ^ (arow&7)) << 4);
            uint32_t ah0,ah1,ah2,ah3, al0,al1,al2,al3;
            LDSM_X4(ah0,ah1,ah2,ah3, sQh + aoff);
            LDSM_X4(al0,al1,al2,al3, sQl + aoff);
            uint32_t bh_[4][4], bl_[4][4];
            #pragma unroll
            for (int nf2 = 0; nf2 < 4; nf2++) {
                const int brow = nf2*16 + lrow;
                const uint32_t boff = brow*256 + ((un>>3)<<7) + (((un&7) ^ (brow&7)) << 4);
                LDSM_X4(bh_[nf2][0], bh_[nf2][1], bh_[nf2][2], bh_[nf2][3], st + boff);
                LDSM_X4(bl_[nf2][0], bl_[nf2][1], bl_[nf2][2], bl_[nf2][3], st + 16384 + boff);
            }
            #pragma unroll
            for (int nf = 0; nf < 8; nf++) {
                const int n2 = nf >> 1, sl = nf & 1;
                MMA16816(sacc[nf], ah0,ah1,ah2,ah3, bh_[n2][sl], bh_[n2][sl+2]);
                MMA16816(sacc[nf], ah0,ah1,ah2,ah3, bl_[n2][sl], bl_[n2][sl+2]);
                MMA16816(sacc[nf], al0,al1,al2,al3, bh_[n2][sl], bh_[n2][sl+2]);
            }
        }

        if (kb >= 2*qb) {
            const int rg0 = qb*128 + wid*16 + r0;
            #pragma unroll
            for (int nf = 0; nf < 8; nf++) {
                const int cg = kb*64 + nf*8 + qd*2;
                if (cg     > rg0)     sacc[nf][0] = -1e30f;
                if (cg + 1 > rg0)     sacc[nf][1] = -1e30f;
                if (cg     > rg0 + 8) sacc[nf][2] = -1e30f;
                if (cg + 1 > rg0 + 8) sacc[nf][3] = -1e30f;
            }
        }

        float mx0 = -1e30f, mx1 = -1e30f;
        #pragma unroll
        for (int nf = 0; nf < 8; nf++) {
            mx0 = fmaxf(mx0, fmaxf(sacc[nf][0], sacc[nf][1]));
            mx1 = fmaxf(mx1, fmaxf(sacc[nf][2], sacc[nf][3]));
        }
        mx0 = fmaxf(mx0, __shfl_xor_sync(0xffffffffu, mx0, 1));
        mx0 = fmaxf(mx0, __shfl_xor_sync(0xffffffffu, mx0, 2));
        mx1 = fmaxf(mx1, __shfl_xor_sync(0xffffffffu, mx1, 1));
        mx1 = fmaxf(mx1, __shfl_xor_sync(0xffffffffu, mx1, 2));
        const float mn0 = fmaxf(m0, mx0), mn1 = fmaxf(m1, mx1);
        const float c0 = exp2f(m0 - mn0), c1 = exp2f(m1 - mn1);
        float s0 = 0.f, s1 = 0.f;
        #pragma unroll
        for (int nf = 0; nf < 8; nf++) {
            sacc[nf][0] = exp2f(sacc[nf][0] - mn0); s0 += sacc[nf][0];
            sacc[nf][1] = exp2f(sacc[nf][1] - mn0); s0 += sacc[nf][1];
            sacc[nf][2] = exp2f(sacc[nf][2] - mn1); s1 += sacc[nf][2];
            sacc[nf][3] = exp2f(sacc[nf][3] - mn1); s1 += sacc[nf][3];
        }
        s0 += __shfl_xor_sync(0xffffffffu, s0, 1);
        s0 += __shfl_xor_sync(0xffffffffu, s0, 2);
        s1 += __shfl_xor_sync(0xffffffffu, s1, 1);
        s1 += __shfl_xor_sync(0xffffffffu, s1, 2);
        l0 = l0*c0 + s0; l1 = l1*c1 + s1; m0 = mn0; m1 = mn1;
        #pragma unroll
        for (int nf = 0; nf < 16; nf++) {
            oacc[nf][0] *= c0; oacc[nf][1] *= c0;
            oacc[nf][2] *= c1; oacc[nf][3] *= c1;
        }

        #pragma unroll
        for (int ks = 0; ks < 4; ks++) {
            uint32_t pah[4], pal[4];
            split_pack2(sacc[2*ks][0],   sacc[2*ks][1],   pah[0], pal[0]);
            split_pack2(sacc[2*ks][2],   sacc[2*ks][3],   pah[1], pal[1]);
            split_pack2(sacc[2*ks+1][0], sacc[2*ks+1][1], pah[2], pal[2]);
            split_pack2(sacc[2*ks+1][2], sacc[2*ks+1][3], pah[3], pal[3]);
            const int un = ks*2 + lu;
            #pragma unroll
            for (int nf2 = 0; nf2 < 8; nf2++) {
                const int vrow = nf2*16 + lrow;
                const uint32_t voff = vrow*128 + ((un ^ (vrow&7)) << 4);
                uint32_t vh0,vh1,vh2,vh3, vl0,vl1,vl2,vl3;
                LDSM_X4(vh0,vh1,vh2,vh3, st + 32768 + voff);
                LDSM_X4(vl0,vl1,vl2,vl3, st + 49152 + voff);
                MMA16816(oacc[nf2*2+0], pah[0],pah[1],pah[2],pah[3], vh0, vh2);
                MMA16816(oacc[nf2*2+0], pah[0],pah[1],pah[2],pah[3], vl0, vl2);
                MMA16816(oacc[nf2*2+0], pal[0],pal[1],pal[2],pal[3], vh0, vh2);
                MMA16816(oacc[nf2*2+1], pah[0],pah[1],pah[2],pah[3], vh1, vh3);
                MMA16816(oacc[nf2*2+1], pah[0],pah[1],pah[2],pah[3], vl1, vl3);
                MMA16816(oacc[nf2*2+1], pal[0],pal[1],pal[2],pal[3], vh1, vh3);
            }
        }
        __syncthreads();
        if (kb + 2 < NKB) LOAD_KV(kb + 2, kb & 1);
    }

    const float inv0 = 1.f / l0, inv1 = 1.f / l1;
    const size_t row0 = qrow0 + wid*16 + r0;
    #pragma unroll
    for (int nf = 0; nf < 16; nf++) {
        const size_t c = (size_t)hoff + nf*8 + qd*2;
        split_store2(Oh, Ol, row0*D_MODEL + c,
                     oacc[nf][0]*inv0, oacc[nf][1]*inv0);
        split_store2(Oh, Ol, (row0+8)*D_MODEL + c,
                     oacc[nf][2]*inv1, oacc[nf][3]*inv1);
    }
    #undef LOAD_KV
}

/* ================= launch ================= */
extern "C" void kernel_launch(void* const* d_in, const int* in_sizes, int n_in,
                              void* d_out, int out_size)
{
    const float* x  = (const float*)d_in[0];
    const float* Wq = (const float*)d_in[1];
    const float* Wk = (const float*)d_in[2];
    const float* Wv = (const float*)d_in[3];
    const float* Wo = (const float*)d_in[4];
    const float* W1 = (const float*)d_in[5];
    const float* W2 = (const float*)d_in[6];
    const float* W3 = (const float*)d_in[7];
    const float* g1 = (const float*)d_in[8];
    const float* g2 = (const float*)d_in[9];
    float* out = (float*)d_out;

    float *v, *res;
    cudaGetSymbolAddress((void**)&v,   g_v);
    cudaGetSymbolAddress((void**)&res, g_res);

    __nv_bfloat16 *xnh,*xnl,*ath,*atl,*f1h,*f1l;
    __nv_bfloat16 *qh,*ql,*kh,*kl,*vth,*vtl;
    __nv_bfloat16 *wqkvh,*wqkvl,*woh,*wol,*w13h,*w13l,*w2h,*w2l;
    cudaGetSymbolAddress((void**)&xnh, g_xnh); cudaGetSymbolAddress((void**)&xnl, g_xnl);
    cudaGetSymbolAddress((void**)&ath, g_ath); cudaGetSymbolAddress((void**)&atl, g_atl);
    cudaGetSymbolAddress((void**)&f1h, g_f1h); cudaGetSymbolAddress((void**)&f1l, g_f1l);
    cudaGetSymbolAddress((void**)&qh,  g_qh);  cudaGetSymbolAddress((void**)&ql,  g_ql);
    cudaGetSymbolAddress((void**)&kh,  g_kh);  cudaGetSymbolAddress((void**)&kl,  g_kl);
    cudaGetSymbolAddress((void**)&vth, g_vth); cudaGetSymbolAddress((void**)&vtl, g_vtl);
    cudaGetSymbolAddress((void**)&wqkvh, g_wqkvh); cudaGetSymbolAddress((void**)&wqkvl, g_wqkvl);
    cudaGetSymbolAddress((void**)&woh, g_woh); cudaGetSymbolAddress((void**)&wol, g_wol);
    cudaGetSymbolAddress((void**)&w13h, g_w13h); cudaGetSymbolAddress((void**)&w13l, g_w13l);
    cudaGetSymbolAddress((void**)&w2h, g_w2h); cudaGetSymbolAddress((void**)&w2l, g_w2l);

    cudaFuncSetAttribute(gemm_kernel<0>,
        cudaFuncAttributeMaxDynamicSharedMemorySize, GEMM_SMEM);
    cudaFuncSetAttribute(gemm_kernel<1>,
        cudaFuncAttributeMaxDynamicSharedMemorySize, GEMM_SMEM);
    cudaFuncSetAttribute(gemm_kernel<2>,
        cudaFuncAttributeMaxDynamicSharedMemorySize, GEMM_SMEM);
    cudaFuncSetAttribute(attn_hmma_kernel,
        cudaFuncAttributeMaxDynamicSharedMemorySize, ATTN_SMEM);

    /* 0. all weight splits in one launch */
    {
        size_t total4 = 4*((size_t)D_MODEL*D_MODEL/4) + 3*((size_t)D_FF*D_MODEL/4);
        megasplit_kernel<<<(unsigned)((total4 + 255)/256), 256>>>(
            Wq, Wk, Wv, Wo, W1, W3, W2,
            wqkvh, wqkvl, woh, wol, w13h, w13l, w2h, w2l);
    }

    /* 1. xn = rmsnorm(x, g1) -> split */
    rmsnorm_split_kernel<<<ROWS, 256>>>(x, g1, xnh, xnl);

    /* 2. merged QKV projection; q/k roped+split, v fp32 */
    gemm_kernel<1><<<dim3(48, ROWS/256), 256, GEMM_SMEM>>>(
        xnh, xnl, wqkvh, wqkvl, v, nullptr, qh, ql, kh, kl,
        ROWS, D_MODEL, D_MODEL);

    /* 3. V transpose + split */
    vtrans_split_kernel<<<dim3(SEQ/32, DK/32, BATCH*NH), 256>>>(v, vth, vtl);

    /* 4. attention */
    attn_hmma_kernel<<<dim3(SEQ/128, BATCH*NH), 256, ATTN_SMEM>>>(
        qh, ql, kh, kl, vth, vtl, ath, atl);

    /* 5. res = x + att @ Wo^T */
    gemm_kernel<0><<<dim3(16, ROWS/256), 256, GEMM_SMEM>>>(
        ath, atl, woh, wol, res, x, nullptr, nullptr, nullptr, nullptr,
        ROWS, D_MODEL, D_MODEL);

    /* 6. xn2 = rmsnorm(res, g2) -> split */
    rmsnorm_split_kernel<<<ROWS, 256>>>(res, g2, xnh, xnl);

    /* 7. merged W13 GEMM + fused swiglu -> h split */
    gemm_kernel<2><<<dim3(86, ROWS/256), 256, GEMM_SMEM>>>(
        xnh, xnl, w13h, w13l, nullptr, nullptr, f1h, f1l, nullptr, nullptr,
        ROWS, D_FF, D_MODEL);

    /* 8. out = res + h @ W2^T */
    gemm_kernel<0><<<dim3(16, ROWS/256), 256, GEMM_SMEM>>>(
        f1h, f1l, w2h, w2l, out, res, nullptr, nullptr, nullptr, nullptr,
        ROWS, D_MODEL, D_FF);
}

// round 12
// speedup vs baseline: 1.6002x; 1.6002x over previous
#include <cuda_runtime.h>
#include <cuda_bf16.h>
#include <cuda_fp16.h>
#include <math.h>
#include <stdint.h>

#define D_MODEL 2048
#define SEQ     2048
#define BATCH   2
#define ROWS    (BATCH*SEQ)     /* 4096 */
#define D_FF    5504
#define NH      16
#define DK      128

/* ================= scratch ================= */
__device__ float g_v  [(size_t)ROWS*D_MODEL];
__device__ float g_res[(size_t)ROWS*D_MODEL];

__device__ __half        g_xnf[(size_t)ROWS*D_MODEL];           /* fp16 activations */
__device__ __nv_bfloat16 g_ath[(size_t)ROWS*D_MODEL];
__device__ __nv_bfloat16 g_atl[(size_t)ROWS*D_MODEL];
__device__ __nv_bfloat16 g_f1h[(size_t)ROWS*D_FF];
__device__ __nv_bfloat16 g_f1l[(size_t)ROWS*D_FF];
__device__ __nv_bfloat16 g_qh [(size_t)ROWS*D_MODEL];
__device__ __nv_bfloat16 g_ql [(size_t)ROWS*D_MODEL];
__device__ __nv_bfloat16 g_kh [(size_t)ROWS*D_MODEL];
__device__ __nv_bfloat16 g_kl [(size_t)ROWS*D_MODEL];
__device__ __nv_bfloat16 g_vth[(size_t)BATCH*NH*DK*SEQ];
__device__ __nv_bfloat16 g_vtl[(size_t)BATCH*NH*DK*SEQ];

__device__ __half        g_wqkv[(size_t)3*D_MODEL*D_MODEL];     /* fp16 weights */
__device__ __half        g_w13 [(size_t)2*D_FF*D_MODEL];
__device__ __nv_bfloat16 g_woh [(size_t)D_MODEL*D_MODEL];
__device__ __nv_bfloat16 g_wol [(size_t)D_MODEL*D_MODEL];
__device__ __nv_bfloat16 g_w2h [(size_t)D_MODEL*D_FF];
__device__ __nv_bfloat16 g_w2l [(size_t)D_MODEL*D_FF];

/* ================= helpers ================= */
__device__ __forceinline__ uint32_t smem_u32(const void* p) {
    uint32_t a;
    asm("{ .reg .u64 t; cvta.to.shared.u64 t, %1; cvt.u32.u64 %0, t; }"
        : "=r"(a) : "l"(p));
    return a;
}

#define LDSM_X4(r0,r1,r2,r3, addr) \
    asm volatile("ldmatrix.sync.aligned.m8n8.x4.shared.b16 {%0,%1,%2,%3}, [%4];" \
        : "=r"(r0),"=r"(r1),"=r"(r2),"=r"(r3) : "r"(addr))

#define MMA16816(d, a0,a1,a2,a3, b0,b1) \
    asm volatile("mma.sync.aligned.m16n8k16.row.col.f32.bf16.bf16.f32 " \
        "{%0,%1,%2,%3}, {%4,%5,%6,%7}, {%8,%9}, {%0,%1,%2,%3};" \
        : "+f"((d)[0]),"+f"((d)[1]),"+f"((d)[2]),"+f"((d)[3]) \
        : "r"(a0),"r"(a1),"r"(a2),"r"(a3), "r"(b0),"r"(b1))

#define MMAF16(d, a0,a1,a2,a3, b0,b1) \
    asm volatile("mma.sync.aligned.m16n8k16.row.col.f32.f16.f16.f32 " \
        "{%0,%1,%2,%3}, {%4,%5,%6,%7}, {%8,%9}, {%0,%1,%2,%3};" \
        : "+f"((d)[0]),"+f"((d)[1]),"+f"((d)[2]),"+f"((d)[3]) \
        : "r"(a0),"r"(a1),"r"(a2),"r"(a3), "r"(b0),"r"(b1))

__device__ __forceinline__ void split_pack2(float x, float y,
                                            uint32_t& h, uint32_t& l) {
    __nv_bfloat16 hx = __float2bfloat16(x), hy = __float2bfloat16(y);
    __nv_bfloat162 hv(hx, hy);
    __nv_bfloat162 lv(__float2bfloat16(x - __bfloat162float(hx)),
                      __float2bfloat16(y - __bfloat162float(hy)));
    h = *reinterpret_cast<uint32_t*>(&hv);
    l = *reinterpret_cast<uint32_t*>(&lv);
}

__device__ __forceinline__ void split_store2(__nv_bfloat16* H, __nv_bfloat16* L,
                                             size_t idx, float x, float y) {
    __nv_bfloat16 hx = __float2bfloat16(x), hy = __float2bfloat16(y);
    __nv_bfloat16 lx = __float2bfloat16(x - __bfloat162float(hx));
    __nv_bfloat16 ly = __float2bfloat16(y - __bfloat162float(hy));
    *reinterpret_cast<__nv_bfloat162*>(H + idx) = __nv_bfloat162(hx, hy);
    *reinterpret_cast<__nv_bfloat162*>(L + idx) = __nv_bfloat162(lx, ly);
}

__device__ __forceinline__ void h16_store2(__half* W, size_t idx, float x, float y) {
    *reinterpret_cast<__half2*>(W + idx) =
        __half2(__float2half_rn(x), __float2half_rn(y));
}

/* ================= mega weight split =================
   Wq,Wk,Wv -> g_wqkv fp16 (concat); Wo -> bf16 h/l; W1,W3 -> g_w13 fp16
   interleaved in 64-row groups; W2 -> bf16 h/l. */
__global__ __launch_bounds__(256) void megasplit_kernel(
    const float* __restrict__ Wq, const float* __restrict__ Wk,
    const float* __restrict__ Wv, const float* __restrict__ Wo,
    const float* __restrict__ W1, const float* __restrict__ W3,
    const float* __restrict__ W2,
    __half* qkvF, __nv_bfloat16* woH, __nv_bfloat16* woL,
    __half* w13F, __nv_bfloat16* w2H, __nv_bfloat16* w2L)
{
    const size_t S1 = (size_t)D_MODEL*D_MODEL/4;
    const size_t S2 = (size_t)D_FF*D_MODEL/4;
    size_t i4 = (size_t)blockIdx.x*256 + threadIdx.x;
    if (i4 >= 4*S1 + 3*S2) return;

    if (i4 < 3*S1) {
        size_t seg = i4 / S1, off = i4 - seg*S1;
        const float* W = (seg == 0) ? Wq : (seg == 1) ? Wk : Wv;
        float4 v = ((const float4*)W)[off];
        h16_store2(qkvF, i4*4,   v.x, v.y);
        h16_store2(qkvF, i4*4+2, v.z, v.w);
    } else if (i4 < 4*S1) {
        size_t off = i4 - 3*S1;
        float4 v = ((const float4*)Wo)[off];
        split_store2(woH, woL, off*4,   v.x, v.y);
        split_store2(woH, woL, off*4+2, v.z, v.w);
    } else if (i4 < 4*S1 + 2*S2) {
        size_t off = i4 - 4*S1;
        int isW3 = off >= S2; if (isW3) off -= S2;
        float4 v = ((const float4*)(isW3 ? W3 : W1))[off];
        size_t r = off >> 9, c = off & 511;
        size_t d = (r >> 6)*128 + (isW3 ? 64 : 0) + (r & 63);
        h16_store2(w13F, (d*512 + c)*4,   v.x, v.y);
        h16_store2(w13F, (d*512 + c)*4+2, v.z, v.w);
    } else {
        size_t off = i4 - 4*S1 - 2*S2;
        float4 v = ((const float4*)W2)[off];
        split_store2(w2H, w2L, off*4,   v.x, v.y);
        split_store2(w2H, w2L, off*4+2, v.z, v.w);
    }
}

/* ================= RMSNorm -> fp16 ================= */
__global__ __launch_bounds__(256) void rmsnorm_f16_kernel(
    const float* __restrict__ X, const float* __restrict__ g,
    __half* __restrict__ Y)
{
    const int row = blockIdx.x;
    const float* x = X + (size_t)row * D_MODEL;

    float ss = 0.f;
    #pragma unroll
    for (int i = threadIdx.x; i < D_MODEL/4; i += 256) {
        float4 v = ((const float4*)x)[i];
        ss += v.x*v.x + v.y*v.y + v.z*v.z + v.w*v.w;
    }
    #pragma unroll
    for (int off = 16; off; off >>= 1)
        ss += __shfl_xor_sync(0xffffffffu, ss, off);
    __shared__ float red[8];
    if ((threadIdx.x & 31) == 0) red[threadIdx.x >> 5] = ss;
    __syncthreads();
    float tot = red[0]+red[1]+red[2]+red[3]+red[4]+red[5]+red[6]+red[7];
    float rinv = rsqrtf(tot * (1.0f / D_MODEL) + 1e-5f);

    #pragma unroll
    for (int i = threadIdx.x; i < D_MODEL/4; i += 256) {
        float4 v = ((const float4*)x)[i];
        float4 gg = ((const float4*)g)[i];
        size_t base = (size_t)row * D_MODEL + i*4;
        h16_store2(Y, base,   v.x*rinv*gg.x, v.y*rinv*gg.y);
        h16_store2(Y, base+2, v.z*rinv*gg.z, v.w*rinv*gg.w);
    }
}

/* ================= fp16 single HMMA GEMM, 256x128 tile, 3-stage =======
   MODE 1: QKV merged; q/k RoPE+split bf16, v fp32
   MODE 2: W13 merged; h = silu(f1)*f3 -> split bf16 */
#define F_STAGE   49152                     /* A 32KB + B 16KB */
#define F_GSTAGES 3
#define F_SMEM    (F_GSTAGES*F_STAGE)       /* 144KB */

template<int MODE>
__global__ __launch_bounds__(256, 1) void gemm16_kernel(
    const __half* __restrict__ A, const __half* __restrict__ B,
    float* __restrict__ C,
    __nv_bfloat16* __restrict__ OH, __nv_bfloat16* __restrict__ OL,
    __nv_bfloat16* __restrict__ KH2, __nv_bfloat16* __restrict__ KL2,
    int M, int N, int K)
{
    extern __shared__ char smem[];
    const uint32_t sb = smem_u32(smem);
    const int tid = threadIdx.x;
    const int wid = tid >> 5, lane = tid & 31;
    const int wr = wid & 3;            /* 4 row groups of 64 */
    const int wc = wid >> 2;           /* 2 col groups of 64 */
    const int NC = K / 64;

    const int rowA = blockIdx.y * 256;
    const int rowB = blockIdx.x * 128;

    const __half* srcA = A + (size_t)rowA * K;
    const __half* srcB = B + (size_t)rowB * K;

    const int r0 = tid >> 3;           /* 0..31 */
    const int u  = tid & 7;

    #define LOAD_STAGE16(chunk, s) do {                                      \
        uint32_t _stb = sb + (s) * F_STAGE;                                  \
        size_t _k0 = (size_t)(chunk) * 64;                                   \
        _Pragma("unroll")                                                    \
        for (int _i = 0; _i < 8; _i++) {                                     \
            int _r = r0 + _i * 32;                                           \
            uint32_t _d = _r * 128 + ((u ^ (_r & 7)) * 16);                  \
            const void* _g = srcA + (size_t)_r * K + _k0 + u * 8;            \
            asm volatile("cp.async.cg.shared.global [%0], [%1], 16;"         \
                         :: "r"(_stb + _d), "l"(_g));                        \
        }                                                                    \
        _Pragma("unroll")                                                    \
        for (int _i = 0; _i < 4; _i++) {                                     \
            int _r = r0 + _i * 32;                                           \
            uint32_t _d = _r * 128 + ((u ^ (_r & 7)) * 16);                  \
            const void* _g = srcB + (size_t)_r * K + _k0 + u * 8;            \
            asm volatile("cp.async.cg.shared.global [%0], [%1], 16;"         \
                         :: "r"(_stb + 32768 + _d), "l"(_g));                \
        }                                                                    \
        asm volatile("cp.async.commit_group;" ::: "memory");                 \
    } while (0)

    LOAD_STAGE16(0, 0);
    if (NC > 1) LOAD_STAGE16(1, 1);
    if (NC > 2) LOAD_STAGE16(2, 2);

    float acc[4][8][4];
    #pragma unroll
    for (int i = 0; i < 4; i++)
        #pragma unroll
        for (int j = 0; j < 8; j++)
            #pragma unroll
            for (int c = 0; c < 4; c++) acc[i][j][c] = 0.f;

    const int lrow = lane & 15;
    const int lu   = lane >> 4;

    for (int j = 0; j < NC; j++) {
        {
            int pend = NC - 1 - j; if (pend > 2) pend = 2;
            if (pend == 2)      asm volatile("cp.async.wait_group 2;" ::: "memory");
            else if (pend == 1) asm volatile("cp.async.wait_group 1;" ::: "memory");
            else                asm volatile("cp.async.wait_group 0;" ::: "memory");
        }
        __syncthreads();

        const uint32_t stb = sb + (j % F_GSTAGES) * F_STAGE;
        const uint32_t tA = stb;
        const uint32_t tB = stb + 32768;

        #pragma unroll
        for (int ks = 0; ks < 4; ks++) {
            const int unit = ks*2 + lu;
            uint32_t a[4][4];
            #pragma unroll
            for (int mf = 0; mf < 4; mf++) {
                const int row = wr*64 + mf*16 + lrow;
                const uint32_t off = row*128 + ((unit ^ (row & 7)) << 4);
                LDSM_X4(a[mf][0], a[mf][1], a[mf][2], a[mf][3], tA + off);
            }
            #pragma unroll
            for (int nf2 = 0; nf2 < 4; nf2++) {
                const int brow = wc*64 + nf2*16 + lrow;
                const uint32_t off = brow*128 + ((unit ^ (brow & 7)) << 4);
                uint32_t b0,b1,b2,b3;
                LDSM_X4(b0,b1,b2,b3, tB + off);
                #pragma unroll
                for (int mf = 0; mf < 4; mf++) {
                    MMAF16(acc[mf][nf2*2+0], a[mf][0],a[mf][1],a[mf][2],a[mf][3], b0, b2);
                    MMAF16(acc[mf][nf2*2+1], a[mf][0],a[mf][1],a[mf][2],a[mf][3], b1, b3);
                }
            }
        }
        __syncthreads();
        if (j + F_GSTAGES < NC) LOAD_STAGE16(j + F_GSTAGES, j % F_GSTAGES);
    }

    const int erowL = wr*64 + (lane >> 2);
    const int ecolL = wc*64 + (lane & 3)*2;

    if (MODE == 1) {
        const int seg = blockIdx.x >> 4;
        const int colT0 = ((blockIdx.x & 15) << 7) + ecolL;
        const float QSC = 0.08838834764831845f * 1.4426950408889634f;
        #pragma unroll
        for (int mf = 0; mf < 4; mf++) {
            #pragma unroll
            for (int half = 0; half < 2; half++) {
                const int rowg = rowA + erowL + mf*16 + half*8;
                const int s = rowg & (SEQ-1);
                #pragma unroll
                for (int nf = 0; nf < 8; nf++) {
                    const int col = colT0 + nf*8;
                    float v0 = acc[mf][nf][half*2+0];
                    float v1 = acc[mf][nf][half*2+1];
                    if (seg == 2) {
                        *(float2*)(C + (size_t)rowg*D_MODEL + col) = make_float2(v0, v1);
                    } else {
                        const int kidx = (col & 127) >> 1;
                        const float freq = expf(-0.14391156831212824f * (float)kidx);
                        float sn, cs;
                        sincosf((float)s * freq, &sn, &cs);
                        float e = v0*cs - v1*sn;
                        float o = v0*sn + v1*cs;
                        if (seg == 0) {
                            split_store2(OH, OL, (size_t)rowg*D_MODEL + col,
                                         e*QSC, o*QSC);
                        } else {
                            split_store2(KH2, KL2, (size_t)rowg*D_MODEL + col, e, o);
                        }
                    }
                }
            }
        }
    } else {
        /* MODE 2: wc=0 f1, wc=1 f3 of same global cols; exchange via smem */
        float* sx = (float*)smem;              /* [256][68] fp32 = 69.6KB */
        __syncthreads();
        if (wc == 1) {
            #pragma unroll
            for (int mf = 0; mf < 4; mf++) {
                #pragma unroll
                for (int half = 0; half < 2; half++) {
                    const int rl = erowL + mf*16 + half*8;
                    #pragma unroll
                    for (int nf = 0; nf < 8; nf++) {
                        const int jj = (ecolL - 64) + nf*8;
                        sx[rl*68 + jj]     = acc[mf][nf][half*2+0];
                        sx[rl*68 + jj + 1] = acc[mf][nf][half*2+1];
                    }
                }
            }
        }
        __syncthreads();
        if (wc == 0) {
            #pragma unroll
            for (int mf = 0; mf < 4; mf++) {
                #pragma unroll
                for (int half = 0; half < 2; half++) {
                    const int rl = erowL + mf*16 + half*8;
                    const size_t rowg = (size_t)(rowA + rl);
                    #pragma unroll
                    for (int nf = 0; nf < 8; nf++) {
                        const int jj = ecolL + nf*8;
                        float a0 = acc[mf][nf][half*2+0];
                        float a1 = acc[mf][nf][half*2+1];
                        float b0 = sx[rl*68 + jj];
                        float b1 = sx[rl*68 + jj + 1];
                        float h0 = a0 / (1.f + expf(-a0)) * b0;
                        float h1 = a1 / (1.f + expf(-a1)) * b1;
                        split_store2(OH, OL,
                                     rowg*D_FF + (size_t)blockIdx.x*64 + jj,
                                     h0, h1);
                    }
                }
            }
        }
    }
    #undef LOAD_STAGE16
}

/* ================= bf16x3 HMMA GEMM, 256x128 tile (residual out) ======= */
#define CHUNK_K     64
#define STAGE_BYTES (2*(256*128) + 2*(128*128))   /* 96KB */
#define GSTAGES     2
#define GEMM_SMEM   (GSTAGES*STAGE_BYTES)

__global__ __launch_bounds__(256, 1) void gemm_bf16x3_kernel(
    const __nv_bfloat16* __restrict__ Ah, const __nv_bfloat16* __restrict__ Al,
    const __nv_bfloat16* __restrict__ Bh, const __nv_bfloat16* __restrict__ Bl,
    float* __restrict__ C, const float* __restrict__ R,
    int M, int N, int K)
{
    extern __shared__ char smem[];
    const uint32_t sb = smem_u32(smem);
    const int tid = threadIdx.x;
    const int wid = tid >> 5, lane = tid & 31;
    const int wr = wid & 3;
    const int wc = wid >> 2;
    const int NC = K / CHUNK_K;

    const int rowA = blockIdx.y * 256;
    const int rowB = blockIdx.x * 128;

    const __nv_bfloat16* srcA_h = Ah + (size_t)rowA * K;
    const __nv_bfloat16* srcA_l = Al + (size_t)rowA * K;
    const __nv_bfloat16* srcB_h = Bh + (size_t)rowB * K;
    const __nv_bfloat16* srcB_l = Bl + (size_t)rowB * K;

    const int r0 = tid >> 3;
    const int u  = tid & 7;

    #define LOAD_STAGE(chunk, s) do {                                        \
        uint32_t _stb = sb + (s) * STAGE_BYTES;                              \
        size_t _k0 = (size_t)(chunk) * CHUNK_K;                              \
        _Pragma("unroll")                                                    \
        for (int _i = 0; _i < 8; _i++) {                                     \
            int _r = r0 + _i * 32;                                           \
            uint32_t _d = _r * 128 + ((u ^ (_r & 7)) * 16);                  \
            const void* _g1 = srcA_h + (size_t)_r * K + _k0 + u * 8;         \
            const void* _g2 = srcA_l + (size_t)_r * K + _k0 + u * 8;         \
            asm volatile("cp.async.cg.shared.global [%0], [%1], 16;"         \
                         :: "r"(_stb + _d), "l"(_g1));                       \
            asm volatile("cp.async.cg.shared.global [%0], [%1], 16;"         \
                         :: "r"(_stb + 32768 + _d), "l"(_g2));               \
        }                                                                    \
        _Pragma("unroll")                                                    \
        for (int _i = 0; _i < 4; _i++) {                                     \
            int _r = r0 + _i * 32;                                           \
            uint32_t _d = _r * 128 + ((u ^ (_r & 7)) * 16);                  \
            const void* _g1 = srcB_h + (size_t)_r * K + _k0 + u * 8;         \
            const void* _g2 = srcB_l + (size_t)_r * K + _k0 + u * 8;         \
            asm volatile("cp.async.cg.shared.global [%0], [%1], 16;"         \
                         :: "r"(_stb + 65536 + _d), "l"(_g1));               \
            asm volatile("cp.async.cg.shared.global [%0], [%1], 16;"         \
                         :: "r"(_stb + 81920 + _d), "l"(_g2));               \
        }                                                                    \
        asm volatile("cp.async.commit_group;" ::: "memory");                 \
    } while (0)

    LOAD_STAGE(0, 0);
    if (NC > 1) LOAD_STAGE(1, 1);

    float acc[4][8][4];
    #pragma unroll
    for (int i = 0; i < 4; i++)
        #pragma unroll
        for (int j = 0; j < 8; j++)
            #pragma unroll
            for (int c = 0; c < 4; c++) acc[i][j][c] = 0.f;

    const int lrow = lane & 15;
    const int lu   = lane >> 4;

    for (int j = 0; j < NC; j++) {
        if (j + 1 < NC) asm volatile("cp.async.wait_group 1;" ::: "memory");
        else            asm volatile("cp.async.wait_group 0;" ::: "memory");
        __syncthreads();

        const uint32_t stb = sb + (j & 1) * STAGE_BYTES;
        const uint32_t tAh = stb;
        const uint32_t tAl = stb + 32768;
        const uint32_t tBh = stb + 65536;
        const uint32_t tBl = stb + 81920;

        #pragma unroll
        for (int ks = 0; ks < 4; ks++) {
            const int unit = ks*2 + lu;
            uint32_t ah[4][4], al[4][4];
            #pragma unroll
            for (int mf = 0; mf < 4; mf++) {
                const int row = wr*64 + mf*16 + lrow;
                const uint32_t off = row*128 + ((unit ^ (row & 7)) << 4);
                LDSM_X4(ah[mf][0], ah[mf][1], ah[mf][2], ah[mf][3], tAh + off);
                LDSM_X4(al[mf][0], al[mf][1], al[mf][2], al[mf][3], tAl + off);
            }
            #pragma unroll
            for (int nf2 = 0; nf2 < 4; nf2++) {
                const int brow = wc*64 + nf2*16 + lrow;
                const uint32_t off = brow*128 + ((unit ^ (brow & 7)) << 4);
                uint32_t bh0,bh1,bh2,bh3, bl0,bl1,bl2,bl3;
                LDSM_X4(bh0,bh1,bh2,bh3, tBh + off);
                LDSM_X4(bl0,bl1,bl2,bl3, tBl + off);
                #pragma unroll
                for (int mf = 0; mf < 4; mf++) {
                    MMA16816(acc[mf][nf2*2+0], ah[mf][0],ah[mf][1],ah[mf][2],ah[mf][3], bh0, bh2);
                    MMA16816(acc[mf][nf2*2+0], ah[mf][0],ah[mf][1],ah[mf][2],ah[mf][3], bl0, bl2);
                    MMA16816(acc[mf][nf2*2+0], al[mf][0],al[mf][1],al[mf][2],al[mf][3], bh0, bh2);
                    MMA16816(acc[mf][nf2*2+1], ah[mf][0],ah[mf][1],ah[mf][2],ah[mf][3], bh1, bh3);
                    MMA16816(acc[mf][nf2*2+1], ah[mf][0],ah[mf][1],ah[mf][2],ah[mf][3], bl1, bl3);
                    MMA16816(acc[mf][nf2*2+1], al[mf][0],al[mf][1],al[mf][2],al[mf][3], bh1, bh3);
                }
            }
        }
        __syncthreads();
        if (j + GSTAGES < NC) LOAD_STAGE(j + GSTAGES, j & 1);
    }

    const int erow = rowA + wr*64 + (lane >> 2);
    const int ecol = rowB + wc*64 + (lane & 3)*2;
    #pragma unroll
    for (int mf = 0; mf < 4; mf++) {
        #pragma unroll
        for (int half = 0; half < 2; half++) {
            const int row = erow + mf*16 + half*8;
            float* crow = C + (size_t)row * N + ecol;
            const float* rrow = R ? (R + (size_t)row * N + ecol) : (const float*)0;
            #pragma unroll
            for (int nf = 0; nf < 8; nf++) {
                float2 v = make_float2(acc[mf][nf][half*2+0], acc[mf][nf][half*2+1]);
                if (rrow) {
                    float2 rv = *(const float2*)(rrow + nf*8);
                    v.x += rv.x; v.y += rv.y;
                }
                *(float2*)(crow + nf*8) = v;
            }
        }
    }
    #undef LOAD_STAGE
}

/* ================= V transpose + split ================= */
__global__ __launch_bounds__(256) void vtrans_split_kernel(
    const float* __restrict__ V, __nv_bfloat16* __restrict__ H,
    __nv_bfloat16* __restrict__ L)
{
    __shared__ float t[32][33];
    const int s0 = blockIdx.x * 32, d0 = blockIdx.y * 32, bh = blockIdx.z;
    const int b = bh >> 4, h = bh & 15;
    const int tx = threadIdx.x & 31, ty = threadIdx.x >> 5;
    #pragma unroll
    for (int j = 0; j < 4; j++) {
        int s = s0 + ty + j*8;
        t[ty + j*8][tx] = V[((size_t)(b*SEQ + s))*D_MODEL + h*DK + d0 + tx];
    }
    __syncthreads();
    #pragma unroll
    for (int j = 0; j < 4; j++) {
        int d = d0 + ty + j*8;
        float val = t[tx][ty + j*8];
        __nv_bfloat16 hi = __float2bfloat16(val);
        __nv_bfloat16 lo = __float2bfloat16(val - __bfloat162float(hi));
        size_t idx = ((size_t)bh*DK + d)*SEQ + s0 + tx;
        H[idx] = hi; L[idx] = lo;
    }
}

/* ================= HMMA causal flash attention (bf16x3) ================= */
#define ATTN_SMEM  (192*1024)

__global__ __launch_bounds__(256, 1) void attn_hmma_kernel(
    const __nv_bfloat16* __restrict__ Qh, const __nv_bfloat16* __restrict__ Ql,
    const __nv_bfloat16* __restrict__ Kh, const __nv_bfloat16* __restrict__ Kl,
    const __nv_bfloat16* __restrict__ Vh, const __nv_bfloat16* __restrict__ Vl,
    __nv_bfloat16* __restrict__ Oh, __nv_bfloat16* __restrict__ Ol)
{
    extern __shared__ char smem[];
    const uint32_t sb  = smem_u32(smem);
    const uint32_t sQh = sb, sQl = sb + 32768;
    const int qb = (int)gridDim.x - 1 - (int)blockIdx.x;
    const int bh = blockIdx.y;
    const int b = bh >> 4, h = bh & 15;
    const int tid = threadIdx.x, wid = tid >> 5, lane = tid & 31;
    const int r0 = lane >> 2, qd = lane & 3, lrow = lane & 15, lu = lane >> 4;

    const size_t qrow0 = (size_t)b*SEQ + (size_t)qb*128;
    const size_t krow0 = (size_t)b*SEQ;
    const int hoff = h*DK;
    const size_t vbase = (size_t)bh*DK*SEQ;
    const int NKB = 2*qb + 2;

    #pragma unroll
    for (int it = 0; it < 8; it++) {
        int lin = it*256 + tid;
        int r = lin >> 4, un = lin & 15;
        uint32_t dsw = r*256 + ((un>>3)<<7) + (((un&7) ^ (r&7)) << 4);
        const void* gh = Qh + (qrow0 + r)*D_MODEL + hoff + un*8;
        const void* gl = Ql + (qrow0 + r)*D_MODEL + hoff + un*8;
        asm volatile("cp.async.cg.shared.global [%0], [%1], 16;" :: "r"(sQh+dsw), "l"(gh));
        asm volatile("cp.async.cg.shared.global [%0], [%1], 16;" :: "r"(sQl+dsw), "l"(gl));
    }

    #define LOAD_KV(kb_, s_) do {                                                  \
        uint32_t _st = sb + 65536 + (uint32_t)(s_)*65536;                          \
        size_t _kr = krow0 + (size_t)(kb_)*64;                                     \
        _Pragma("unroll")                                                          \
        for (int _it = 0; _it < 4; _it++) {                                        \
            int _lin = _it*256 + tid;                                              \
            int _r = _lin >> 4, _un = _lin & 15;                                   \
            uint32_t _d = _r*256 + ((_un>>3)<<7) + (((_un&7) ^ (_r&7)) << 4);      \
            const void* _g1 = Kh + (_kr + _r)*D_MODEL + hoff + _un*8;              \
            const void* _g2 = Kl + (_kr + _r)*D_MODEL + hoff + _un*8;              \
            asm volatile("cp.async.cg.shared.global [%0], [%1], 16;"               \
                         :: "r"(_st+_d), "l"(_g1));                                \
            asm volatile("cp.async.cg.shared.global [%0], [%1], 16;"               \
                         :: "r"(_st+16384+_d), "l"(_g2));                          \
        }                                                                          \
        _Pragma("unroll")                                                          \
        for (int _it = 0; _it < 4; _it++) {                                        \
            int _lin = _it*256 + tid;                                              \
            int _r = _lin >> 3, _u = _lin & 7;                                     \
            uint32_t _d = _r*128 + ((_u ^ (_r&7)) << 4);                           \
            const void* _g1 = Vh + vbase + (size_t)_r*SEQ + (size_t)(kb_)*64 + _u*8; \
            const void* _g2 = Vl + vbase + (size_t)_r*SEQ + (size_t)(kb_)*64 + _u*8; \
            asm volatile("cp.async.cg.shared.global [%0], [%1], 16;"               \
                         :: "r"(_st+32768+_d), "l"(_g1));                          \
            asm volatile("cp.async.cg.shared.global [%0], [%1], 16;"               \
                         :: "r"(_st+49152+_d), "l"(_g2));                          \
        }                                                                          \
        asm volatile("cp.async.commit_group;" ::: "memory");                       \
    } while (0)

    LOAD_KV(0, 0);
    LOAD_KV(1, 1);

    float m0 = -1e30f, m1 = -1e30f, l0 = 0.f, l1 = 0.f;
    float oacc[16][4];
    #pragma unroll
    for (int i = 0; i < 16; i++)
        #pragma unroll
        for (int c = 0; c < 4; c++) oacc[i][c] = 0.f;

    for (int kb = 0; kb < NKB; kb++) {
        if (kb + 1 < NKB) asm volatile("cp.async.wait_group 1;" ::: "memory");
        else              asm volatile("cp.async.wait_group 0;" ::: "memory");
        __syncthreads();
        const uint32_t st = sb + 65536 + (uint32_t)(kb & 1)*65536;

        float sacc[8][4];
        #pragma unroll
        for (int i = 0; i < 8; i++)
            #pragma unroll
            for (int c = 0; c < 4; c++) sacc[i][c] = 0.f;

        #pragma unroll
        for (int kk = 0; kk < 8; kk++) {
            const int un = kk*2 + lu;
            const int arow = wid*16 + lrow;
            const uint32_t aoff = arow*256 + ((un>>3)<<7) + (((un&7) ^ (arow&7)) << 4);
            uint32_t ah0,ah1,ah2,ah3, al0,al1,al2,al3;
            LDSM_X4(ah0,ah1,ah2,ah3, sQh + aoff);
            LDSM_X4(al0,al1,al2,al3, sQl + aoff);
            uint32_t bh_[4][4], bl_[4][4];
            #pragma unroll
            for (int nf2 = 0; nf2 < 4; nf2++) {
                const int brow = nf2*16 + lrow;
                const uint32_t boff = brow*256 + ((un>>3)<<7) + (((un&7) ^ (brow&7)) << 4);
                LDSM_X4(bh_[nf2][0], bh_[nf2][1], bh_[nf2][2], bh_[nf2][3], st + boff);
                LDSM_X4(bl_[nf2][0], bl_[nf2][1], bl_[nf2][2], bl_[nf2][3], st + 16384 + boff);
            }
            #pragma unroll
            for (int nf = 0; nf < 8; nf++) {
                const int n2 = nf >> 1, sl = nf & 1;
                MMA16816(sacc[nf], ah0,ah1,ah2,ah3, bh_[n2][sl], bh_[n2][sl+2]);
                MMA16816(sacc[nf], ah0,ah1,ah2,ah3, bl_[n2][sl], bl_[n2][sl+2]);
                MMA16816(sacc[nf], al0,al1,al2,al3, bh_[n2][sl], bh_[n2][sl+2]);
            }
        }

        if (kb >= 2*qb) {
            const int rg0 = qb*128 + wid*16 + r0;
            #pragma unroll
            for (int nf = 0; nf < 8; nf++) {
                const int cg = kb*64 + nf*8 + qd*2;
                if (cg     > rg0)     sacc[nf][0] = -1e30f;
                if (cg + 1 > rg0)     sacc[nf][1] = -1e30f;
                if (cg     > rg0 + 8) sacc[nf][2] = -1e30f;
                if (cg + 1 > rg0 + 8) sacc[nf][3] = -1e30f;
            }
        }

        float mx0 = -1e30f, mx1 = -1e30f;
        #pragma unroll
        for (int nf = 0; nf < 8; nf++) {
            mx0 = fmaxf(mx0, fmaxf(sacc[nf][0], sacc[nf][1]));
            mx1 = fmaxf(mx1, fmaxf(sacc[nf][2], sacc[nf][3]));
        }
        mx0 = fmaxf(mx0, __shfl_xor_sync(0xffffffffu, mx0, 1));
        mx0 = fmaxf(mx0, __shfl_xor_sync(0xffffffffu, mx0, 2));
        mx1 = fmaxf(mx1, __shfl_xor_sync(0xffffffffu, mx1, 1));
        mx1 = fmaxf(mx1, __shfl_xor_sync(0xffffffffu, mx1, 2));
        const float mn0 = fmaxf(m0, mx0), mn1 = fmaxf(m1, mx1);
        const float c0 = exp2f(m0 - mn0), c1 = exp2f(m1 - mn1);
        float s0 = 0.f, s1 = 0.f;
        #pragma unroll
        for (int nf = 0; nf < 8; nf++) {
            sacc[nf][0] = exp2f(sacc[nf][0] - mn0); s0 += sacc[nf][0];
            sacc[nf][1] = exp2f(sacc[nf][1] - mn0); s0 += sacc[nf][1];
            sacc[nf][2] = exp2f(sacc[nf][2] - mn1); s1 += sacc[nf][2];
            sacc[nf][3] = exp2f(sacc[nf][3] - mn1); s1 += sacc[nf][3];
        }
        s0 += __shfl_xor_sync(0xffffffffu, s0, 1);
        s0 += __shfl_xor_sync(0xffffffffu, s0, 2);
        s1 += __shfl_xor_sync(0xffffffffu, s1, 1);
        s1 += __shfl_xor_sync(0xffffffffu, s1, 2);
        l0 = l0*c0 + s0; l1 = l1*c1 + s1; m0 = mn0; m1 = mn1;
        #pragma unroll
        for (int nf = 0; nf < 16; nf++) {
            oacc[nf][0] *= c0; oacc[nf][1] *= c0;
            oacc[nf][2] *= c1; oacc[nf][3] *= c1;
        }

        #pragma unroll
        for (int ks = 0; ks < 4; ks++) {
            uint32_t pah[4], pal[4];
            split_pack2(sacc[2*ks][0],   sacc[2*ks][1],   pah[0], pal[0]);
            split_pack2(sacc[2*ks][2],   sacc[2*ks][3],   pah[1], pal[1]);
            split_pack2(sacc[2*ks+1][0], sacc[2*ks+1][1], pah[2], pal[2]);
            split_pack2(sacc[2*ks+1][2], sacc[2*ks+1][3], pah[3], pal[3]);
            const int un = ks*2 + lu;
            #pragma unroll
            for (int nf2 = 0; nf2 < 8; nf2++) {
                const int vrow = nf2*16 + lrow;
                const uint32_t voff = vrow*128 + ((un ^ (vrow&7)) << 4);
                uint32_t vh0,vh1,vh2,vh3, vl0,vl1,vl2,vl3;
                LDSM_X4(vh0,vh1,vh2,vh3, st + 32768 + voff);
                LDSM_X4(vl0,vl1,vl2,vl3, st + 49152 + voff);
                MMA16816(oacc[nf2*2+0], pah[0],pah[1],pah[2],pah[3], vh0, vh2);
                MMA16816(oacc[nf2*2+0], pah[0],pah[1],pah[2],pah[3], vl0, vl2);
                MMA16816(oacc[nf2*2+0], pal[0],pal[1],pal[2],pal[3], vh0, vh2);
                MMA16816(oacc[nf2*2+1], pah[0],pah[1],pah[2],pah[3], vh1, vh3);
                MMA16816(oacc[nf2*2+1], pah[0],pah[1],pah[2],pah[3], vl1, vl3);
                MMA16816(oacc[nf2*2+1], pal[0],pal[1],pal[2],pal[3], vh1, vh3);
            }
        }
        __syncthreads();
        if (kb + 2 < NKB) LOAD_KV(kb + 2, kb & 1);
    }

    const float inv0 = 1.f / l0, inv1 = 1.f / l1;
    const size_t row0 = qrow0 + wid*16 + r0;
    #pragma unroll
    for (int nf = 0; nf < 16; nf++) {
        const size_t c = (size_t)hoff + nf*8 + qd*2;
        split_store2(Oh, Ol, row0*D_MODEL + c,
                     oacc[nf][0]*inv0, oacc[nf][1]*inv0);
        split_store2(Oh, Ol, (row0+8)*D_MODEL + c,
                     oacc[nf][2]*inv1, oacc[nf][3]*inv1);
    }
    #undef LOAD_KV
}

/* ================= launch ================= */
extern "C" void kernel_launch(void* const* d_in, const int* in_sizes, int n_in,
                              void* d_out, int out_size)
{
    const float* x  = (const float*)d_in[0];
    const float* Wq = (const float*)d_in[1];
    const float* Wk = (const float*)d_in[2];
    const float* Wv = (const float*)d_in[3];
    const float* Wo = (const float*)d_in[4];
    const float* W1 = (const float*)d_in[5];
    const float* W2 = (const float*)d_in[6];
    const float* W3 = (const float*)d_in[7];
    const float* g1 = (const float*)d_in[8];
    const float* g2 = (const float*)d_in[9];
    float* out = (float*)d_out;

    float *v, *res;
    cudaGetSymbolAddress((void**)&v,   g_v);
    cudaGetSymbolAddress((void**)&res, g_res);

    __half *xnf, *wqkv, *w13;
    __nv_bfloat16 *ath,*atl,*f1h,*f1l,*qh,*ql,*kh,*kl,*vth,*vtl;
    __nv_bfloat16 *woh,*wol,*w2h,*w2l;
    cudaGetSymbolAddress((void**)&xnf, g_xnf);
    cudaGetSymbolAddress((void**)&wqkv, g_wqkv);
    cudaGetSymbolAddress((void**)&w13, g_w13);
    cudaGetSymbolAddress((void**)&ath, g_ath); cudaGetSymbolAddress((void**)&atl, g_atl);
    cudaGetSymbolAddress((void**)&f1h, g_f1h); cudaGetSymbolAddress((void**)&f1l, g_f1l);
    cudaGetSymbolAddress((void**)&qh,  g_qh);  cudaGetSymbolAddress((void**)&ql,  g_ql);
    cudaGetSymbolAddress((void**)&kh,  g_kh);  cudaGetSymbolAddress((void**)&kl,  g_kl);
    cudaGetSymbolAddress((void**)&vth, g_vth); cudaGetSymbolAddress((void**)&vtl, g_vtl);
    cudaGetSymbolAddress((void**)&woh, g_woh); cudaGetSymbolAddress((void**)&wol, g_wol);
    cudaGetSymbolAddress((void**)&w2h, g_w2h); cudaGetSymbolAddress((void**)&w2l, g_w2l);

    cudaFuncSetAttribute(gemm_bf16x3_kernel,
        cudaFuncAttributeMaxDynamicSharedMemorySize, GEMM_SMEM);
    cudaFuncSetAttribute(gemm16_kernel<1>,
        cudaFuncAttributeMaxDynamicSharedMemorySize, F_SMEM);
    cudaFuncSetAttribute(gemm16_kernel<2>,
        cudaFuncAttributeMaxDynamicSharedMemorySize, F_SMEM);
    cudaFuncSetAttribute(attn_hmma_kernel,
        cudaFuncAttributeMaxDynamicSharedMemorySize, ATTN_SMEM);

    /* 0. all weight splits in one launch */
    {
        size_t total4 = 4*((size_t)D_MODEL*D_MODEL/4) + 3*((size_t)D_FF*D_MODEL/4);
        megasplit_kernel<<<(unsigned)((total4 + 255)/256), 256>>>(
            Wq, Wk, Wv, Wo, W1, W3, W2,
            wqkv, woh, wol, w13, w2h, w2l);
    }

    /* 1. xn = rmsnorm(x, g1) -> fp16 */
    rmsnorm_f16_kernel<<<ROWS, 256>>>(x, g1, xnf);

    /* 2. merged QKV projection (fp16); q/k roped+split bf16, v fp32 */
    gemm16_kernel<1><<<dim3(48, ROWS/256), 256, F_SMEM>>>(
        xnf, wqkv, v, qh, ql, kh, kl, ROWS, D_MODEL, D_MODEL);

    /* 3. V transpose + split */
    vtrans_split_kernel<<<dim3(SEQ/32, DK/32, BATCH*NH), 256>>>(v, vth, vtl);

    /* 4. attention (bf16x3) */
    attn_hmma_kernel<<<dim3(SEQ/128, BATCH*NH), 256, ATTN_SMEM>>>(
        qh, ql, kh, kl, vth, vtl, ath, atl);

    /* 5. res = x + att @ Wo^T (bf16x3) */
    gemm_bf16x3_kernel<<<dim3(16, ROWS/256), 256, GEMM_SMEM>>>(
        ath, atl, woh, wol, res, x, ROWS, D_MODEL, D_MODEL);

    /* 6. xn2 = rmsnorm(res, g2) -> fp16 */
    rmsnorm_f16_kernel<<<ROWS, 256>>>(res, g2, xnf);

    /* 7. merged W13 GEMM (fp16) + fused swiglu -> h split bf16 */
    gemm16_kernel<2><<<dim3(86, ROWS/256), 256, F_SMEM>>>(
        xnf, w13, nullptr, f1h, f1l, nullptr, nullptr, ROWS, D_FF, D_MODEL);

    /* 8. out = res + h @ W2^T (bf16x3) */
    gemm_bf16x3_kernel<<<dim3(16, ROWS/256), 256, GEMM_SMEM>>>(
        f1h, f1l, w2h, w2l, out, res, ROWS, D_MODEL, D_FF);
}

// round 13
// speedup vs baseline: 2.2077x; 1.3797x over previous
#include <cuda_runtime.h>
#include <cuda_bf16.h>
#include <cuda_fp16.h>
#include <math.h>
#include <stdint.h>

#define D_MODEL 2048
#define SEQ     2048
#define BATCH   2
#define ROWS    (BATCH*SEQ)     /* 4096 */
#define D_FF    5504
#define NH      16
#define DK      128

/* ================= scratch ================= */
__device__ float g_v  [(size_t)ROWS*D_MODEL];
__device__ float g_res[(size_t)ROWS*D_MODEL];

__device__ __half        g_xnf[(size_t)ROWS*D_MODEL];   /* fp16 activations */
__device__ __half        g_atf[(size_t)ROWS*D_MODEL];   /* attention out fp16 */
__device__ __half        g_f1f[(size_t)ROWS*D_FF];      /* swiglu out fp16 */
__device__ __nv_bfloat16 g_qh [(size_t)ROWS*D_MODEL];
__device__ __nv_bfloat16 g_ql [(size_t)ROWS*D_MODEL];
__device__ __nv_bfloat16 g_kh [(size_t)ROWS*D_MODEL];
__device__ __nv_bfloat16 g_kl [(size_t)ROWS*D_MODEL];
__device__ __nv_bfloat16 g_vth[(size_t)BATCH*NH*DK*SEQ];
__device__ __nv_bfloat16 g_vtl[(size_t)BATCH*NH*DK*SEQ];

__device__ __half g_wqkv[(size_t)3*D_MODEL*D_MODEL];    /* fp16 weights */
__device__ __half g_wo  [(size_t)D_MODEL*D_MODEL];
__device__ __half g_w13 [(size_t)2*D_FF*D_MODEL];
__device__ __half g_w2  [(size_t)D_MODEL*D_FF];

/* ================= helpers ================= */
__device__ __forceinline__ uint32_t smem_u32(const void* p) {
    uint32_t a;
    asm("{ .reg .u64 t; cvta.to.shared.u64 t, %1; cvt.u32.u64 %0, t; }"
        : "=r"(a) : "l"(p));
    return a;
}

#define LDSM_X4(r0,r1,r2,r3, addr) \
    asm volatile("ldmatrix.sync.aligned.m8n8.x4.shared.b16 {%0,%1,%2,%3}, [%4];" \
        : "=r"(r0),"=r"(r1),"=r"(r2),"=r"(r3) : "r"(addr))

#define MMA16816(d, a0,a1,a2,a3, b0,b1) \
    asm volatile("mma.sync.aligned.m16n8k16.row.col.f32.bf16.bf16.f32 " \
        "{%0,%1,%2,%3}, {%4,%5,%6,%7}, {%8,%9}, {%0,%1,%2,%3};" \
        : "+f"((d)[0]),"+f"((d)[1]),"+f"((d)[2]),"+f"((d)[3]) \
        : "r"(a0),"r"(a1),"r"(a2),"r"(a3), "r"(b0),"r"(b1))

#define MMAF16(d, a0,a1,a2,a3, b0,b1) \
    asm volatile("mma.sync.aligned.m16n8k16.row.col.f32.f16.f16.f32 " \
        "{%0,%1,%2,%3}, {%4,%5,%6,%7}, {%8,%9}, {%0,%1,%2,%3};" \
        : "+f"((d)[0]),"+f"((d)[1]),"+f"((d)[2]),"+f"((d)[3]) \
        : "r"(a0),"r"(a1),"r"(a2),"r"(a3), "r"(b0),"r"(b1))

__device__ __forceinline__ void split_pack2(float x, float y,
                                            uint32_t& h, uint32_t& l) {
    __nv_bfloat16 hx = __float2bfloat16(x), hy = __float2bfloat16(y);
    __nv_bfloat162 hv(hx, hy);
    __nv_bfloat162 lv(__float2bfloat16(x - __bfloat162float(hx)),
                      __float2bfloat16(y - __bfloat162float(hy)));
    h = *reinterpret_cast<uint32_t*>(&hv);
    l = *reinterpret_cast<uint32_t*>(&lv);
}

__device__ __forceinline__ void split_store2(__nv_bfloat16* H, __nv_bfloat16* L,
                                             size_t idx, float x, float y) {
    __nv_bfloat16 hx = __float2bfloat16(x), hy = __float2bfloat16(y);
    __nv_bfloat16 lx = __float2bfloat16(x - __bfloat162float(hx));
    __nv_bfloat16 ly = __float2bfloat16(y - __bfloat162float(hy));
    *reinterpret_cast<__nv_bfloat162*>(H + idx) = __nv_bfloat162(hx, hy);
    *reinterpret_cast<__nv_bfloat162*>(L + idx) = __nv_bfloat162(lx, ly);
}

__device__ __forceinline__ void h16_store2(__half* W, size_t idx, float x, float y) {
    *reinterpret_cast<__half2*>(W + idx) =
        __half2(__float2half_rn(x), __float2half_rn(y));
}

/* ================= mega weight split (all fp16) =================
   Wq,Wk,Wv -> g_wqkv (concat); Wo -> g_wo; W1,W3 -> g_w13 interleaved in
   64-row groups; W2 -> g_w2. */
__global__ __launch_bounds__(256) void megasplit_kernel(
    const float* __restrict__ Wq, const float* __restrict__ Wk,
    const float* __restrict__ Wv, const float* __restrict__ Wo,
    const float* __restrict__ W1, const float* __restrict__ W3,
    const float* __restrict__ W2,
    __half* qkvF, __half* woF, __half* w13F, __half* w2F)
{
    const size_t S1 = (size_t)D_MODEL*D_MODEL/4;
    const size_t S2 = (size_t)D_FF*D_MODEL/4;
    size_t i4 = (size_t)blockIdx.x*256 + threadIdx.x;
    if (i4 >= 4*S1 + 3*S2) return;

    float4 v; __half* F; size_t d4;
    if (i4 < 3*S1) {
        size_t seg = i4 / S1, off = i4 - seg*S1;
        const float* W = (seg == 0) ? Wq : (seg == 1) ? Wk : Wv;
        v = ((const float4*)W)[off];
        F = qkvF; d4 = i4;
    } else if (i4 < 4*S1) {
        size_t off = i4 - 3*S1;
        v = ((const float4*)Wo)[off];
        F = woF; d4 = off;
    } else if (i4 < 4*S1 + 2*S2) {
        size_t off = i4 - 4*S1;
        int isW3 = off >= S2; if (isW3) off -= S2;
        v = ((const float4*)(isW3 ? W3 : W1))[off];
        size_t r = off >> 9, c = off & 511;
        size_t d = (r >> 6)*128 + (isW3 ? 64 : 0) + (r & 63);
        F = w13F; d4 = d*512 + c;
    } else {
        size_t off = i4 - 4*S1 - 2*S2;
        v = ((const float4*)W2)[off];
        F = w2F; d4 = off;
    }
    h16_store2(F, d4*4,   v.x, v.y);
    h16_store2(F, d4*4+2, v.z, v.w);
}

/* ================= RMSNorm -> fp16 ================= */
__global__ __launch_bounds__(256) void rmsnorm_f16_kernel(
    const float* __restrict__ X, const float* __restrict__ g,
    __half* __restrict__ Y)
{
    const int row = blockIdx.x;
    const float* x = X + (size_t)row * D_MODEL;

    float ss = 0.f;
    #pragma unroll
    for (int i = threadIdx.x; i < D_MODEL/4; i += 256) {
        float4 v = ((const float4*)x)[i];
        ss += v.x*v.x + v.y*v.y + v.z*v.z + v.w*v.w;
    }
    #pragma unroll
    for (int off = 16; off; off >>= 1)
        ss += __shfl_xor_sync(0xffffffffu, ss, off);
    __shared__ float red[8];
    if ((threadIdx.x & 31) == 0) red[threadIdx.x >> 5] = ss;
    __syncthreads();
    float tot = red[0]+red[1]+red[2]+red[3]+red[4]+red[5]+red[6]+red[7];
    float rinv = rsqrtf(tot * (1.0f / D_MODEL) + 1e-5f);

    #pragma unroll
    for (int i = threadIdx.x; i < D_MODEL/4; i += 256) {
        float4 v = ((const float4*)x)[i];
        float4 gg = ((const float4*)g)[i];
        size_t base = (size_t)row * D_MODEL + i*4;
        h16_store2(Y, base,   v.x*rinv*gg.x, v.y*rinv*gg.y);
        h16_store2(Y, base+2, v.z*rinv*gg.z, v.w*rinv*gg.w);
    }
}

/* ================= fp16 single HMMA GEMM, 256x128 tile, 3-stage =======
   MODE 0: C = A B^T + R (fp32 out)
   MODE 1: QKV merged; q/k RoPE+split bf16, v fp32
   MODE 2: W13 merged; h = silu(f1)*f3 -> fp16 */
#define F_STAGE   49152                     /* A 32KB + B 16KB */
#define F_GSTAGES 3
#define F_SMEM    (F_GSTAGES*F_STAGE)       /* 144KB */

template<int MODE>
__global__ __launch_bounds__(256, 1) void gemm16_kernel(
    const __half* __restrict__ A, const __half* __restrict__ B,
    float* __restrict__ C, const float* __restrict__ R,
    __nv_bfloat16* __restrict__ OH, __nv_bfloat16* __restrict__ OL,
    __nv_bfloat16* __restrict__ KH2, __nv_bfloat16* __restrict__ KL2,
    __half* __restrict__ OF,
    int M, int N, int K)
{
    extern __shared__ char smem[];
    const uint32_t sb = smem_u32(smem);
    const int tid = threadIdx.x;
    const int wid = tid >> 5, lane = tid & 31;
    const int wr = wid & 3;            /* 4 row groups of 64 */
    const int wc = wid >> 2;           /* 2 col groups of 64 */
    const int NC = K / 64;

    const int rowA = blockIdx.y * 256;
    const int rowB = blockIdx.x * 128;

    const __half* srcA = A + (size_t)rowA * K;
    const __half* srcB = B + (size_t)rowB * K;

    const int r0 = tid >> 3;           /* 0..31 */
    const int u  = tid & 7;

    #define LOAD_STAGE16(chunk, s) do {                                      \
        uint32_t _stb = sb + (s) * F_STAGE;                                  \
        size_t _k0 = (size_t)(chunk) * 64;                                   \
        _Pragma("unroll")                                                    \
        for (int _i = 0; _i < 8; _i++) {                                     \
            int _r = r0 + _i * 32;                                           \
            uint32_t _d = _r * 128 + ((u ^ (_r & 7)) * 16);                  \
            const void* _g = srcA + (size_t)_r * K + _k0 + u * 8;            \
            asm volatile("cp.async.cg.shared.global [%0], [%1], 16;"         \
                         :: "r"(_stb + _d), "l"(_g));                        \
        }                                                                    \
        _Pragma("unroll")                                                    \
        for (int _i = 0; _i < 4; _i++) {                                     \
            int _r = r0 + _i * 32;                                           \
            uint32_t _d = _r * 128 + ((u ^ (_r & 7)) * 16);                  \
            const void* _g = srcB + (size_t)_r * K + _k0 + u * 8;            \
            asm volatile("cp.async.cg.shared.global [%0], [%1], 16;"         \
                         :: "r"(_stb + 32768 + _d), "l"(_g));                \
        }                                                                    \
        asm volatile("cp.async.commit_group;" ::: "memory");                 \
    } while (0)

    LOAD_STAGE16(0, 0);
    if (NC > 1) LOAD_STAGE16(1, 1);
    if (NC > 2) LOAD_STAGE16(2, 2);

    float acc[4][8][4];
    #pragma unroll
    for (int i = 0; i < 4; i++)
        #pragma unroll
        for (int j = 0; j < 8; j++)
            #pragma unroll
            for (int c = 0; c < 4; c++) acc[i][j][c] = 0.f;

    const int lrow = lane & 15;
    const int lu   = lane >> 4;

    for (int j = 0; j < NC; j++) {
        {
            int pend = NC - 1 - j; if (pend > 2) pend = 2;
            if (pend == 2)      asm volatile("cp.async.wait_group 2;" ::: "memory");
            else if (pend == 1) asm volatile("cp.async.wait_group 1;" ::: "memory");
            else                asm volatile("cp.async.wait_group 0;" ::: "memory");
        }
        __syncthreads();

        const uint32_t stb = sb + (j % F_GSTAGES) * F_STAGE;
        const uint32_t tA = stb;
        const uint32_t tB = stb + 32768;

        #pragma unroll
        for (int ks = 0; ks < 4; ks++) {
            const int unit = ks*2 + lu;
            uint32_t a[4][4];
            #pragma unroll
            for (int mf = 0; mf < 4; mf++) {
                const int row = wr*64 + mf*16 + lrow;
                const uint32_t off = row*128 + ((unit ^ (row & 7)) << 4);
                LDSM_X4(a[mf][0], a[mf][1], a[mf][2], a[mf][3], tA + off);
            }
            #pragma unroll
            for (int nf2 = 0; nf2 < 4; nf2++) {
                const int brow = wc*64 + nf2*16 + lrow;
                const uint32_t off = brow*128 + ((unit ^ (brow & 7)) << 4);
                uint32_t b0,b1,b2,b3;
                LDSM_X4(b0,b1,b2,b3, tB + off);
                #pragma unroll
                for (int mf = 0; mf < 4; mf++) {
                    MMAF16(acc[mf][nf2*2+0], a[mf][0],a[mf][1],a[mf][2],a[mf][3], b0, b2);
                    MMAF16(acc[mf][nf2*2+1], a[mf][0],a[mf][1],a[mf][2],a[mf][3], b1, b3);
                }
            }
        }
        __syncthreads();
        if (j + F_GSTAGES < NC) LOAD_STAGE16(j + F_GSTAGES, j % F_GSTAGES);
    }

    const int erowL = wr*64 + (lane >> 2);
    const int ecolL = wc*64 + (lane & 3)*2;

    if (MODE == 0) {
        const int erow = rowA + erowL;
        const int ecol = rowB + ecolL;
        #pragma unroll
        for (int mf = 0; mf < 4; mf++) {
            #pragma unroll
            for (int half = 0; half < 2; half++) {
                const int row = erow + mf*16 + half*8;
                float* crow = C + (size_t)row * N + ecol;
                const float* rrow = R + (size_t)row * N + ecol;
                #pragma unroll
                for (int nf = 0; nf < 8; nf++) {
                    float2 v = make_float2(acc[mf][nf][half*2+0], acc[mf][nf][half*2+1]);
                    float2 rv = *(const float2*)(rrow + nf*8);
                    v.x += rv.x; v.y += rv.y;
                    *(float2*)(crow + nf*8) = v;
                }
            }
        }
    } else if (MODE == 1) {
        const int seg = blockIdx.x >> 4;
        const int colT0 = ((blockIdx.x & 15) << 7) + ecolL;
        const float QSC = 0.08838834764831845f * 1.4426950408889634f;
        #pragma unroll
        for (int mf = 0; mf < 4; mf++) {
            #pragma unroll
            for (int half = 0; half < 2; half++) {
                const int rowg = rowA + erowL + mf*16 + half*8;
                const int s = rowg & (SEQ-1);
                #pragma unroll
                for (int nf = 0; nf < 8; nf++) {
                    const int col = colT0 + nf*8;
                    float v0 = acc[mf][nf][half*2+0];
                    float v1 = acc[mf][nf][half*2+1];
                    if (seg == 2) {
                        *(float2*)(C + (size_t)rowg*D_MODEL + col) = make_float2(v0, v1);
                    } else {
                        const int kidx = (col & 127) >> 1;
                        const float freq = expf(-0.14391156831212824f * (float)kidx);
                        float sn, cs;
                        sincosf((float)s * freq, &sn, &cs);
                        float e = v0*cs - v1*sn;
                        float o = v0*sn + v1*cs;
                        if (seg == 0) {
                            split_store2(OH, OL, (size_t)rowg*D_MODEL + col,
                                         e*QSC, o*QSC);
                        } else {
                            split_store2(KH2, KL2, (size_t)rowg*D_MODEL + col, e, o);
                        }
                    }
                }
            }
        }
    } else {
        /* MODE 2: wc=0 f1, wc=1 f3 of same global cols; exchange via smem */
        float* sx = (float*)smem;              /* [256][68] fp32 = 69.6KB */
        __syncthreads();
        if (wc == 1) {
            #pragma unroll
            for (int mf = 0; mf < 4; mf++) {
                #pragma unroll
                for (int half = 0; half < 2; half++) {
                    const int rl = erowL + mf*16 + half*8;
                    #pragma unroll
                    for (int nf = 0; nf < 8; nf++) {
                        const int jj = (ecolL - 64) + nf*8;
                        sx[rl*68 + jj]     = acc[mf][nf][half*2+0];
                        sx[rl*68 + jj + 1] = acc[mf][nf][half*2+1];
                    }
                }
            }
        }
        __syncthreads();
        if (wc == 0) {
            #pragma unroll
            for (int mf = 0; mf < 4; mf++) {
                #pragma unroll
                for (int half = 0; half < 2; half++) {
                    const int rl = erowL + mf*16 + half*8;
                    const size_t rowg = (size_t)(rowA + rl);
                    #pragma unroll
                    for (int nf = 0; nf < 8; nf++) {
                        const int jj = ecolL + nf*8;
                        float a0 = acc[mf][nf][half*2+0];
                        float a1 = acc[mf][nf][half*2+1];
                        float b0 = sx[rl*68 + jj];
                        float b1 = sx[rl*68 + jj + 1];
                        float h0 = a0 / (1.f + expf(-a0)) * b0;
                        float h1 = a1 / (1.f + expf(-a1)) * b1;
                        h16_store2(OF, rowg*D_FF + (size_t)blockIdx.x*64 + jj,
                                   h0, h1);
                    }
                }
            }
        }
    }
    #undef LOAD_STAGE16
}

/* ================= V transpose + split ================= */
__global__ __launch_bounds__(256) void vtrans_split_kernel(
    const float* __restrict__ V, __nv_bfloat16* __restrict__ H,
    __nv_bfloat16* __restrict__ L)
{
    __shared__ float t[32][33];
    const int s0 = blockIdx.x * 32, d0 = blockIdx.y * 32, bh = blockIdx.z;
    const int b = bh >> 4, h = bh & 15;
    const int tx = threadIdx.x & 31, ty = threadIdx.x >> 5;
    #pragma unroll
    for (int j = 0; j < 4; j++) {
        int s = s0 + ty + j*8;
        t[ty + j*8][tx] = V[((size_t)(b*SEQ + s))*D_MODEL + h*DK + d0 + tx];
    }
    __syncthreads();
    #pragma unroll
    for (int j = 0; j < 4; j++) {
        int d = d0 + ty + j*8;
        float val = t[tx][ty + j*8];
        __nv_bfloat16 hi = __float2bfloat16(val);
        __nv_bfloat16 lo = __float2bfloat16(val - __bfloat162float(hi));
        size_t idx = ((size_t)bh*DK + d)*SEQ + s0 + tx;
        H[idx] = hi; L[idx] = lo;
    }
}

/* ================= HMMA causal flash attention (bf16x3) ================= */
#define ATTN_SMEM  (192*1024)

__global__ __launch_bounds__(256, 1) void attn_hmma_kernel(
    const __nv_bfloat16* __restrict__ Qh, const __nv_bfloat16* __restrict__ Ql,
    const __nv_bfloat16* __restrict__ Kh, const __nv_bfloat16* __restrict__ Kl,
    const __nv_bfloat16* __restrict__ Vh, const __nv_bfloat16* __restrict__ Vl,
    __half* __restrict__ Of)
{
    extern __shared__ char smem[];
    const uint32_t sb  = smem_u32(smem);
    const uint32_t sQh = sb, sQl = sb + 32768;
    const int qb = (int)gridDim.x - 1 - (int)blockIdx.x;
    const int bh = blockIdx.y;
    const int b = bh >> 4, h = bh & 15;
    const int tid = threadIdx.x, wid = tid >> 5, lane = tid & 31;
    const int r0 = lane >> 2, qd = lane & 3, lrow = lane & 15, lu = lane >> 4;

    const size_t qrow0 = (size_t)b*SEQ + (size_t)qb*128;
    const size_t krow0 = (size_t)b*SEQ;
    const int hoff = h*DK;
    const size_t vbase = (size_t)bh*DK*SEQ;
    const int NKB = 2*qb + 2;

    #pragma unroll
    for (int it = 0; it < 8; it++) {
        int lin = it*256 + tid;
        int r = lin >> 4, un = lin & 15;
        uint32_t dsw = r*256 + ((un>>3)<<7) + (((un&7) ^ (r&7)) << 4);
        const void* gh = Qh + (qrow0 + r)*D_MODEL + hoff + un*8;
        const void* gl = Ql + (qrow0 + r)*D_MODEL + hoff + un*8;
        asm volatile("cp.async.cg.shared.global [%0], [%1], 16;" :: "r"(sQh+dsw), "l"(gh));
        asm volatile("cp.async.cg.shared.global [%0], [%1], 16;" :: "r"(sQl+dsw), "l"(gl));
    }

    #define LOAD_KV(kb_, s_) do {                                                  \
        uint32_t _st = sb + 65536 + (uint32_t)(s_)*65536;                          \
        size_t _kr = krow0 + (size_t)(kb_)*64;                                     \
        _Pragma("unroll")                                                          \
        for (int _it = 0; _it < 4; _it++) {                                        \
            int _lin = _it*256 + tid;                                              \
            int _r = _lin >> 4, _un = _lin & 15;                                   \
            uint32_t _d = _r*256 + ((_un>>3)<<7) + (((_un&7) ^ (_r&7)) << 4);      \
            const void* _g1 = Kh + (_kr + _r)*D_MODEL + hoff + _un*8;              \
            const void* _g2 = Kl + (_kr + _r)*D_MODEL + hoff + _un*8;              \
            asm volatile("cp.async.cg.shared.global [%0], [%1], 16;"               \
                         :: "r"(_st+_d), "l"(_g1));                                \
            asm volatile("cp.async.cg.shared.global [%0], [%1], 16;"               \
                         :: "r"(_st+16384+_d), "l"(_g2));                          \
        }                                                                          \
        _Pragma("unroll")                                                          \
        for (int _it = 0; _it < 4; _it++) {                                        \
            int _lin = _it*256 + tid;                                              \
            int _r = _lin >> 3, _u = _lin & 7;                                     \
            uint32_t _d = _r*128 + ((_u ^ (_r&7)) << 4);                           \
            const void* _g1 = Vh + vbase + (size_t)_r*SEQ + (size_t)(kb_)*64 + _u*8; \
            const void* _g2 = Vl + vbase + (size_t)_r*SEQ + (size_t)(kb_)*64 + _u*8; \
            asm volatile("cp.async.cg.shared.global [%0], [%1], 16;"               \
                         :: "r"(_st+32768+_d), "l"(_g1));                          \
            asm volatile("cp.async.cg.shared.global [%0], [%1], 16;"               \
                         :: "r"(_st+49152+_d), "l"(_g2));                          \
        }                                                                          \
        asm volatile("cp.async.commit_group;" ::: "memory");                       \
    } while (0)

    LOAD_KV(0, 0);
    LOAD_KV(1, 1);

    float m0 = -1e30f, m1 = -1e30f, l0 = 0.f, l1 = 0.f;
    float oacc[16][4];
    #pragma unroll
    for (int i = 0; i < 16; i++)
        #pragma unroll
        for (int c = 0; c < 4; c++) oacc[i][c] = 0.f;

    for (int kb = 0; kb < NKB; kb++) {
        if (kb + 1 < NKB) asm volatile("cp.async.wait_group 1;" ::: "memory");
        else              asm volatile("cp.async.wait_group 0;" ::: "memory");
        __syncthreads();
        const uint32_t st = sb + 65536 + (uint32_t)(kb & 1)*65536;

        float sacc[8][4];
        #pragma unroll
        for (int i = 0; i < 8; i++)
            #pragma unroll
            for (int c = 0; c < 4; c++) sacc[i][c] = 0.f;

        #pragma unroll
        for (int kk = 0; kk < 8; kk++) {
            const int un = kk*2 + lu;
            const int arow = wid*16 + lrow;
            const uint32_t aoff = arow*256 + ((un>>3)<<7) + (((un&7) ^ (arow&7)) << 4);
            uint32_t ah0,ah1,ah2,ah3, al0,al1,al2,al3;
            LDSM_X4(ah0,ah1,ah2,ah3, sQh + aoff);
            LDSM_X4(al0,al1,al2,al3, sQl + aoff);
            uint32_t bh_[4][4], bl_[4][4];
            #pragma unroll
            for (int nf2 = 0; nf2 < 4; nf2++) {
                const int brow = nf2*16 + lrow;
                const uint32_t boff = brow*256 + ((un>>3)<<7) + (((un&7) ^ (brow&7)) << 4);
                LDSM_X4(bh_[nf2][0], bh_[nf2][1], bh_[nf2][2], bh_[nf2][3], st + boff);
                LDSM_X4(bl_[nf2][0], bl_[nf2][1], bl_[nf2][2], bl_[nf2][3], st + 16384 + boff);
            }
            #pragma unroll
            for (int nf = 0; nf < 8; nf++) {
                const int n2 = nf >> 1, sl = nf & 1;
                MMA16816(sacc[nf], ah0,ah1,ah2,ah3, bh_[n2][sl], bh_[n2][sl+2]);
                MMA16816(sacc[nf], ah0,ah1,ah2,ah3, bl_[n2][sl], bl_[n2][sl+2]);
                MMA16816(sacc[nf], al0,al1,al2,al3, bh_[n2][sl], bh_[n2][sl+2]);
            }
        }

        if (kb >= 2*qb) {
            const int rg0 = qb*128 + wid*16 + r0;
            #pragma unroll
            for (int nf = 0; nf < 8; nf++) {
                const int cg = kb*64 + nf*8 + qd*2;
                if (cg     > rg0)     sacc[nf][0] = -1e30f;
                if (cg + 1 > rg0)     sacc[nf][1] = -1e30f;
                if (cg     > rg0 + 8) sacc[nf][2] = -1e30f;
                if (cg + 1 > rg0 + 8) sacc[nf][3] = -1e30f;
            }
        }

        float mx0 = -1e30f, mx1 = -1e30f;
        #pragma unroll
        for (int nf = 0; nf < 8; nf++) {
            mx0 = fmaxf(mx0, fmaxf(sacc[nf][0], sacc[nf][1]));
            mx1 = fmaxf(mx1, fmaxf(sacc[nf][2], sacc[nf][3]));
        }
        mx0 = fmaxf(mx0, __shfl_xor_sync(0xffffffffu, mx0, 1));
        mx0 = fmaxf(mx0, __shfl_xor_sync(0xffffffffu, mx0, 2));
        mx1 = fmaxf(mx1, __shfl_xor_sync(0xffffffffu, mx1, 1));
        mx1 = fmaxf(mx1, __shfl_xor_sync(0xffffffffu, mx1, 2));
        const float mn0 = fmaxf(m0, mx0), mn1 = fmaxf(m1, mx1);
        const float c0 = exp2f(m0 - mn0), c1 = exp2f(m1 - mn1);
        float s0 = 0.f, s1 = 0.f;
        #pragma unroll
        for (int nf = 0; nf < 8; nf++) {
            sacc[nf][0] = exp2f(sacc[nf][0] - mn0); s0 += sacc[nf][0];
            sacc[nf][1] = exp2f(sacc[nf][1] - mn0); s0 += sacc[nf][1];
            sacc[nf][2] = exp2f(sacc[nf][2] - mn1); s1 += sacc[nf][2];
            sacc[nf][3] = exp2f(sacc[nf][3] - mn1); s1 += sacc[nf][3];
        }
        s0 += __shfl_xor_sync(0xffffffffu, s0, 1);
        s0 += __shfl_xor_sync(0xffffffffu, s0, 2);
        s1 += __shfl_xor_sync(0xffffffffu, s1, 1);
        s1 += __shfl_xor_sync(0xffffffffu, s1, 2);
        l0 = l0*c0 + s0; l1 = l1*c1 + s1; m0 = mn0; m1 = mn1;
        #pragma unroll
        for (int nf = 0; nf < 16; nf++) {
            oacc[nf][0] *= c0; oacc[nf][1] *= c0;
            oacc[nf][2] *= c1; oacc[nf][3] *= c1;
        }

        #pragma unroll
        for (int ks = 0; ks < 4; ks++) {
            uint32_t pah[4], pal[4];
            split_pack2(sacc[2*ks][0],   sacc[2*ks][1],   pah[0], pal[0]);
            split_pack2(sacc[2*ks][2],   sacc[2*ks][3],   pah[1], pal[1]);
            split_pack2(sacc[2*ks+1][0], sacc[2*ks+1][1], pah[2], pal[2]);
            split_pack2(sacc[2*ks+1][2], sacc[2*ks+1][3], pah[3], pal[3]);
            const int un = ks*2 + lu;
            #pragma unroll
            for (int nf2 = 0; nf2 < 8; nf2++) {
                const int vrow = nf2*16 + lrow;
                const uint32_t voff = vrow*128 + ((un ^ (vrow&7)) << 4);
                uint32_t vh0,vh1,vh2,vh3, vl0,vl1,vl2,vl3;
                LDSM_X4(vh0,vh1,vh2,vh3, st + 32768 + voff);
                LDSM_X4(vl0,vl1,vl2,vl3, st + 49152 + voff);
                MMA16816(oacc[nf2*2+0], pah[0],pah[1],pah[2],pah[3], vh0, vh2);
                MMA16816(oacc[nf2*2+0], pah[0],pah[1],pah[2],pah[3], vl0, vl2);
                MMA16816(oacc[nf2*2+0], pal[0],pal[1],pal[2],pal[3], vh0, vh2);
                MMA16816(oacc[nf2*2+1], pah[0],pah[1],pah[2],pah[3], vh1, vh3);
                MMA16816(oacc[nf2*2+1], pah[0],pah[1],pah[2],pah[3], vl1, vl3);
                MMA16816(oacc[nf2*2+1], pal[0],pal[1],pal[2],pal[3], vh1, vh3);
            }
        }
        __syncthreads();
        if (kb + 2 < NKB) LOAD_KV(kb + 2, kb & 1);
    }

    const float inv0 = 1.f / l0, inv1 = 1.f / l1;
    const size_t row0 = qrow0 + wid*16 + r0;
    #pragma unroll
    for (int nf = 0; nf < 16; nf++) {
        const size_t c = (size_t)hoff + nf*8 + qd*2;
        h16_store2(Of, row0*D_MODEL + c,
                   oacc[nf][0]*inv0, oacc[nf][1]*inv0);
        h16_store2(Of, (row0+8)*D_MODEL + c,
                   oacc[nf][2]*inv1, oacc[nf][3]*inv1);
    }
    #undef LOAD_KV
}

/* ================= launch ================= */
extern "C" void kernel_launch(void* const* d_in, const int* in_sizes, int n_in,
                              void* d_out, int out_size)
{
    const float* x  = (const float*)d_in[0];
    const float* Wq = (const float*)d_in[1];
    const float* Wk = (const float*)d_in[2];
    const float* Wv = (const float*)d_in[3];
    const float* Wo = (const float*)d_in[4];
    const float* W1 = (const float*)d_in[5];
    const float* W2 = (const float*)d_in[6];
    const float* W3 = (const float*)d_in[7];
    const float* g1 = (const float*)d_in[8];
    const float* g2 = (const float*)d_in[9];
    float* out = (float*)d_out;

    float *v, *res;
    cudaGetSymbolAddress((void**)&v,   g_v);
    cudaGetSymbolAddress((void**)&res, g_res);

    __half *xnf, *atf, *f1f, *wqkv, *wo, *w13, *w2;
    __nv_bfloat16 *qh,*ql,*kh,*kl,*vth,*vtl;
    cudaGetSymbolAddress((void**)&xnf, g_xnf);
    cudaGetSymbolAddress((void**)&atf, g_atf);
    cudaGetSymbolAddress((void**)&f1f, g_f1f);
    cudaGetSymbolAddress((void**)&wqkv, g_wqkv);
    cudaGetSymbolAddress((void**)&wo,  g_wo);
    cudaGetSymbolAddress((void**)&w13, g_w13);
    cudaGetSymbolAddress((void**)&w2,  g_w2);
    cudaGetSymbolAddress((void**)&qh,  g_qh);  cudaGetSymbolAddress((void**)&ql,  g_ql);
    cudaGetSymbolAddress((void**)&kh,  g_kh);  cudaGetSymbolAddress((void**)&kl,  g_kl);
    cudaGetSymbolAddress((void**)&vth, g_vth); cudaGetSymbolAddress((void**)&vtl, g_vtl);

    cudaFuncSetAttribute(gemm16_kernel<0>,
        cudaFuncAttributeMaxDynamicSharedMemorySize, F_SMEM);
    cudaFuncSetAttribute(gemm16_kernel<1>,
        cudaFuncAttributeMaxDynamicSharedMemorySize, F_SMEM);
    cudaFuncSetAttribute(gemm16_kernel<2>,
        cudaFuncAttributeMaxDynamicSharedMemorySize, F_SMEM);
    cudaFuncSetAttribute(attn_hmma_kernel,
        cudaFuncAttributeMaxDynamicSharedMemorySize, ATTN_SMEM);

    /* 0. all weight conversions in one launch */
    {
        size_t total4 = 4*((size_t)D_MODEL*D_MODEL/4) + 3*((size_t)D_FF*D_MODEL/4);
        megasplit_kernel<<<(unsigned)((total4 + 255)/256), 256>>>(
            Wq, Wk, Wv, Wo, W1, W3, W2, wqkv, wo, w13, w2);
    }

    /* 1. xn = rmsnorm(x, g1) -> fp16 */
    rmsnorm_f16_kernel<<<ROWS, 256>>>(x, g1, xnf);

    /* 2. merged QKV projection (fp16); q/k roped+split bf16, v fp32 */
    gemm16_kernel<1><<<dim3(48, ROWS/256), 256, F_SMEM>>>(
        xnf, wqkv, v, nullptr, qh, ql, kh, kl, nullptr,
        ROWS, D_MODEL, D_MODEL);

    /* 3. V transpose + split */
    vtrans_split_kernel<<<dim3(SEQ/32, DK/32, BATCH*NH), 256>>>(v, vth, vtl);

    /* 4. attention (bf16x3) -> fp16 out */
    attn_hmma_kernel<<<dim3(SEQ/128, BATCH*NH), 256, ATTN_SMEM>>>(
        qh, ql, kh, kl, vth, vtl, atf);

    /* 5. res = x + att @ Wo^T (fp16) */
    gemm16_kernel<0><<<dim3(16, ROWS/256), 256, F_SMEM>>>(
        atf, wo, res, x, nullptr, nullptr, nullptr, nullptr, nullptr,
        ROWS, D_MODEL, D_MODEL);

    /* 6. xn2 = rmsnorm(res, g2) -> fp16 */
    rmsnorm_f16_kernel<<<ROWS, 256>>>(res, g2, xnf);

    /* 7. merged W13 GEMM (fp16) + fused swiglu -> fp16 h */
    gemm16_kernel<2><<<dim3(86, ROWS/256), 256, F_SMEM>>>(
        xnf, w13, nullptr, nullptr, nullptr, nullptr, nullptr, nullptr, f1f,
        ROWS, D_FF, D_MODEL);

    /* 8. out = res + h @ W2^T (fp16) */
    gemm16_kernel<0><<<dim3(16, ROWS/256), 256, F_SMEM>>>(
        f1f, w2, out, res, nullptr, nullptr, nullptr, nullptr, nullptr,
        ROWS, D_MODEL, D_FF);
}

// round 15
// speedup vs baseline: 2.5094x; 1.1367x over previous
#include <cuda_runtime.h>
#include <cuda_bf16.h>
#include <cuda_fp16.h>
#include <math.h>
#include <stdint.h>

#define D_MODEL 2048
#define SEQ     2048
#define BATCH   2
#define ROWS    (BATCH*SEQ)     /* 4096 */
#define D_FF    5504
#define NH      16
#define DK      128

/* ================= scratch ================= */
__device__ float g_v  [(size_t)ROWS*D_MODEL];
__device__ float g_res[(size_t)ROWS*D_MODEL];

__device__ __half g_xnf[(size_t)ROWS*D_MODEL];   /* fp16 activations */
__device__ __half g_atf[(size_t)ROWS*D_MODEL];   /* attention out */
__device__ __half g_f1f[(size_t)ROWS*D_FF];      /* swiglu out */
__device__ __half g_qf [(size_t)ROWS*D_MODEL];   /* q (roped, scaled) */
__device__ __half g_kf [(size_t)ROWS*D_MODEL];   /* k (roped) */
__device__ __half g_vtf[(size_t)BATCH*NH*DK*SEQ];/* v transposed */

__device__ __half g_wqkv[(size_t)3*D_MODEL*D_MODEL];
__device__ __half g_wo  [(size_t)D_MODEL*D_MODEL];
__device__ __half g_w13 [(size_t)2*D_FF*D_MODEL];
__device__ __half g_w2  [(size_t)D_MODEL*D_FF];

/* ================= helpers ================= */
__device__ __forceinline__ uint32_t smem_u32(const void* p) {
    uint32_t a;
    asm("{ .reg .u64 t; cvta.to.shared.u64 t, %1; cvt.u32.u64 %0, t; }"
        : "=r"(a) : "l"(p));
    return a;
}

#define LDSM_X4(r0,r1,r2,r3, addr) \
    asm volatile("ldmatrix.sync.aligned.m8n8.x4.shared.b16 {%0,%1,%2,%3}, [%4];" \
        : "=r"(r0),"=r"(r1),"=r"(r2),"=r"(r3) : "r"(addr))

#define MMAF16(d, a0,a1,a2,a3, b0,b1) \
    asm volatile("mma.sync.aligned.m16n8k16.row.col.f32.f16.f16.f32 " \
        "{%0,%1,%2,%3}, {%4,%5,%6,%7}, {%8,%9}, {%0,%1,%2,%3};" \
        : "+f"((d)[0]),"+f"((d)[1]),"+f"((d)[2]),"+f"((d)[3]) \
        : "r"(a0),"r"(a1),"r"(a2),"r"(a3), "r"(b0),"r"(b1))

__device__ __forceinline__ void h16_store2(__half* W, size_t idx, float x, float y) {
    *reinterpret_cast<__half2*>(W + idx) =
        __half2(__float2half_rn(x), __float2half_rn(y));
}

__device__ __forceinline__ uint32_t pack_h2(float x, float y) {
    __half2 h(__float2half_rn(x), __float2half_rn(y));
    return *reinterpret_cast<uint32_t*>(&h);
}

/* ================= mega weight convert (all fp16) ================= */
__global__ __launch_bounds__(256) void megasplit_kernel(
    const float* __restrict__ Wq, const float* __restrict__ Wk,
    const float* __restrict__ Wv, const float* __restrict__ Wo,
    const float* __restrict__ W1, const float* __restrict__ W3,
    const float* __restrict__ W2,
    __half* qkvF, __half* woF, __half* w13F, __half* w2F)
{
    const size_t S1 = (size_t)D_MODEL*D_MODEL/4;
    const size_t S2 = (size_t)D_FF*D_MODEL/4;
    size_t i4 = (size_t)blockIdx.x*256 + threadIdx.x;
    if (i4 >= 4*S1 + 3*S2) return;

    float4 v; __half* F; size_t d4;
    if (i4 < 3*S1) {
        size_t seg = i4 / S1, off = i4 - seg*S1;
        const float* W = (seg == 0) ? Wq : (seg == 1) ? Wk : Wv;
        v = ((const float4*)W)[off];
        F = qkvF; d4 = i4;
    } else if (i4 < 4*S1) {
        size_t off = i4 - 3*S1;
        v = ((const float4*)Wo)[off];
        F = woF; d4 = off;
    } else if (i4 < 4*S1 + 2*S2) {
        size_t off = i4 - 4*S1;
        int isW3 = off >= S2; if (isW3) off -= S2;
        v = ((const float4*)(isW3 ? W3 : W1))[off];
        size_t r = off >> 9, c = off & 511;
        size_t d = (r >> 6)*128 + (isW3 ? 64 : 0) + (r & 63);
        F = w13F; d4 = d*512 + c;
    } else {
        size_t off = i4 - 4*S1 - 2*S2;
        v = ((const float4*)W2)[off];
        F = w2F; d4 = off;
    }
    h16_store2(F, d4*4,   v.x, v.y);
    h16_store2(F, d4*4+2, v.z, v.w);
}

/* ================= RMSNorm -> fp16 ================= */
__global__ __launch_bounds__(256) void rmsnorm_f16_kernel(
    const float* __restrict__ X, const float* __restrict__ g,
    __half* __restrict__ Y)
{
    const int row = blockIdx.x;
    const float* x = X + (size_t)row * D_MODEL;

    float ss = 0.f;
    #pragma unroll
    for (int i = threadIdx.x; i < D_MODEL/4; i += 256) {
        float4 v = ((const float4*)x)[i];
        ss += v.x*v.x + v.y*v.y + v.z*v.z + v.w*v.w;
    }
    #pragma unroll
    for (int off = 16; off; off >>= 1)
        ss += __shfl_xor_sync(0xffffffffu, ss, off);
    __shared__ float red[8];
    if ((threadIdx.x & 31) == 0) red[threadIdx.x >> 5] = ss;
    __syncthreads();
    float tot = red[0]+red[1]+red[2]+red[3]+red[4]+red[5]+red[6]+red[7];
    float rinv = rsqrtf(tot * (1.0f / D_MODEL) + 1e-5f);

    #pragma unroll
    for (int i = threadIdx.x; i < D_MODEL/4; i += 256) {
        float4 v = ((const float4*)x)[i];
        float4 gg = ((const float4*)g)[i];
        size_t base = (size_t)row * D_MODEL + i*4;
        h16_store2(Y, base,   v.x*rinv*gg.x, v.y*rinv*gg.y);
        h16_store2(Y, base+2, v.z*rinv*gg.z, v.w*rinv*gg.w);
    }
}

/* ================= fp16 HMMA GEMM, 256x128 tile, 3-stage =======
   MODE 0: C = A B^T + R (fp32 out)
   MODE 1: QKV merged; q (RoPE*QSC) -> OF, k (RoPE) -> OF2, v -> C fp32
   MODE 2: W13 merged; h = silu(f1)*f3 -> OF */
#define F_STAGE   49152                     /* A 32KB + B 16KB */
#define F_GSTAGES 3
#define F_SMEM    (F_GSTAGES*F_STAGE)       /* 144KB */

template<int MODE>
__global__ __launch_bounds__(256, 1) void gemm16_kernel(
    const __half* __restrict__ A, const __half* __restrict__ B,
    float* __restrict__ C, const float* __restrict__ R,
    __half* __restrict__ OF, __half* __restrict__ OF2,
    int M, int N, int K)
{
    extern __shared__ char smem[];
    const uint32_t sb = smem_u32(smem);
    const int tid = threadIdx.x;
    const int wid = tid >> 5, lane = tid & 31;
    const int wr = wid & 3;
    const int wc = wid >> 2;
    const int NC = K / 64;

    const int rowA = blockIdx.y * 256;
    const int rowB = blockIdx.x * 128;

    const __half* srcA = A + (size_t)rowA * K;
    const __half* srcB = B + (size_t)rowB * K;

    const int r0 = tid >> 3;
    const int u  = tid & 7;

    #define LOAD_STAGE16(chunk, s) do {                                      \
        uint32_t _stb = sb + (s) * F_STAGE;                                  \
        size_t _k0 = (size_t)(chunk) * 64;                                   \
        _Pragma("unroll")                                                    \
        for (int _i = 0; _i < 8; _i++) {                                     \
            int _r = r0 + _i * 32;                                           \
            uint32_t _d = _r * 128 + ((u ^ (_r & 7)) * 16);                  \
            const void* _g = srcA + (size_t)_r * K + _k0 + u * 8;            \
            asm volatile("cp.async.cg.shared.global [%0], [%1], 16;"         \
                         :: "r"(_stb + _d), "l"(_g));                        \
        }                                                                    \
        _Pragma("unroll")                                                    \
        for (int _i = 0; _i < 4; _i++) {                                     \
            int _r = r0 + _i * 32;                                           \
            uint32_t _d = _r * 128 + ((u ^ (_r & 7)) * 16);                  \
            const void* _g = srcB + (size_t)_r * K + _k0 + u * 8;            \
            asm volatile("cp.async.cg.shared.global [%0], [%1], 16;"         \
                         :: "r"(_stb + 32768 + _d), "l"(_g));                \
        }                                                                    \
        asm volatile("cp.async.commit_group;" ::: "memory");                 \
    } while (0)

    LOAD_STAGE16(0, 0);
    if (NC > 1) LOAD_STAGE16(1, 1);
    if (NC > 2) LOAD_STAGE16(2, 2);

    float acc[4][8][4];
    #pragma unroll
    for (int i = 0; i < 4; i++)
        #pragma unroll
        for (int j = 0; j < 8; j++)
            #pragma unroll
            for (int c = 0; c < 4; c++) acc[i][j][c] = 0.f;

    const int lrow = lane & 15;
    const int lu   = lane >> 4;

    for (int j = 0; j < NC; j++) {
        {
            int pend = NC - 1 - j; if (pend > 2) pend = 2;
            if (pend == 2)      asm volatile("cp.async.wait_group 2;" ::: "memory");
            else if (pend == 1) asm volatile("cp.async.wait_group 1;" ::: "memory");
            else                asm volatile("cp.async.wait_group 0;" ::: "memory");
        }
        __syncthreads();

        const uint32_t stb = sb + (j % F_GSTAGES) * F_STAGE;
        const uint32_t tA = stb;
        const uint32_t tB = stb + 32768;

        #pragma unroll
        for (int ks = 0; ks < 4; ks++) {
            const int unit = ks*2 + lu;
            uint32_t a[4][4];
            #pragma unroll
            for (int mf = 0; mf < 4; mf++) {
                const int row = wr*64 + mf*16 + lrow;
                const uint32_t off = row*128 + ((unit ^ (row & 7)) << 4);
                LDSM_X4(a[mf][0], a[mf][1], a[mf][2], a[mf][3], tA + off);
            }
            #pragma unroll
            for (int nf2 = 0; nf2 < 4; nf2++) {
                const int brow = wc*64 + nf2*16 + lrow;
                const uint32_t off = brow*128 + ((unit ^ (brow & 7)) << 4);
                uint32_t b0,b1,b2,b3;
                LDSM_X4(b0,b1,b2,b3, tB + off);
                #pragma unroll
                for (int mf = 0; mf < 4; mf++) {
                    MMAF16(acc[mf][nf2*2+0], a[mf][0],a[mf][1],a[mf][2],a[mf][3], b0, b2);
                    MMAF16(acc[mf][nf2*2+1], a[mf][0],a[mf][1],a[mf][2],a[mf][3], b1, b3);
                }
            }
        }
        __syncthreads();
        if (j + F_GSTAGES < NC) LOAD_STAGE16(j + F_GSTAGES, j % F_GSTAGES);
    }

    const int erowL = wr*64 + (lane >> 2);
    const int ecolL = wc*64 + (lane & 3)*2;

    if (MODE == 0) {
        const int erow = rowA + erowL;
        const int ecol = rowB + ecolL;
        #pragma unroll
        for (int mf = 0; mf < 4; mf++) {
            #pragma unroll
            for (int half = 0; half < 2; half++) {
                const int row = erow + mf*16 + half*8;
                float* crow = C + (size_t)row * N + ecol;
                const float* rrow = R + (size_t)row * N + ecol;
                #pragma unroll
                for (int nf = 0; nf < 8; nf++) {
                    float2 v = make_float2(acc[mf][nf][half*2+0], acc[mf][nf][half*2+1]);
                    float2 rv = *(const float2*)(rrow + nf*8);
                    v.x += rv.x; v.y += rv.y;
                    *(float2*)(crow + nf*8) = v;
                }
            }
        }
    } else if (MODE == 1) {
        const int seg = blockIdx.x >> 4;
        const int colT0 = ((blockIdx.x & 15) << 7) + ecolL;
        const float QSC = 0.08838834764831845f * 1.4426950408889634f;
        #pragma unroll
        for (int mf = 0; mf < 4; mf++) {
            #pragma unroll
            for (int half = 0; half < 2; half++) {
                const int rowg = rowA + erowL + mf*16 + half*8;
                const int s = rowg & (SEQ-1);
                #pragma unroll
                for (int nf = 0; nf < 8; nf++) {
                    const int col = colT0 + nf*8;
                    float v0 = acc[mf][nf][half*2+0];
                    float v1 = acc[mf][nf][half*2+1];
                    if (seg == 2) {
                        *(float2*)(C + (size_t)rowg*D_MODEL + col) = make_float2(v0, v1);
                    } else {
                        const int kidx = (col & 127) >> 1;
                        const float freq = expf(-0.14391156831212824f * (float)kidx);
                        float sn, cs;
                        sincosf((float)s * freq, &sn, &cs);
                        float e = v0*cs - v1*sn;
                        float o = v0*sn + v1*cs;
                        if (seg == 0) {
                            h16_store2(OF, (size_t)rowg*D_MODEL + col, e*QSC, o*QSC);
                        } else {
                            h16_store2(OF2, (size_t)rowg*D_MODEL + col, e, o);
                        }
                    }
                }
            }
        }
    } else {
        /* MODE 2: wc=0 f1, wc=1 f3 of same global cols; exchange via smem */
        float* sx = (float*)smem;
        __syncthreads();
        if (wc == 1) {
            #pragma unroll
            for (int mf = 0; mf < 4; mf++) {
                #pragma unroll
                for (int half = 0; half < 2; half++) {
                    const int rl = erowL + mf*16 + half*8;
                    #pragma unroll
                    for (int nf = 0; nf < 8; nf++) {
                        const int jj = (ecolL - 64) + nf*8;
                        sx[rl*68 + jj]     = acc[mf][nf][half*2+0];
                        sx[rl*68 + jj + 1] = acc[mf][nf][half*2+1];
                    }
                }
            }
        }
        __syncthreads();
        if (wc == 0) {
            #pragma unroll
            for (int mf = 0; mf < 4; mf++) {
                #pragma unroll
                for (int half = 0; half < 2; half++) {
                    const int rl = erowL + mf*16 + half*8;
                    const size_t rowg = (size_t)(rowA + rl);
                    #pragma unroll
                    for (int nf = 0; nf < 8; nf++) {
                        const int jj = ecolL + nf*8;
                        float a0 = acc[mf][nf][half*2+0];
                        float a1 = acc[mf][nf][half*2+1];
                        float b0 = sx[rl*68 + jj];
                        float b1 = sx[rl*68 + jj + 1];
                        float h0 = a0 / (1.f + expf(-a0)) * b0;
                        float h1 = a1 / (1.f + expf(-a1)) * b1;
                        h16_store2(OF, rowg*D_FF + (size_t)blockIdx.x*64 + jj,
                                   h0, h1);
                    }
                }
            }
        }
    }
    #undef LOAD_STAGE16
}

/* ================= V transpose -> fp16 ================= */
__global__ __launch_bounds__(256) void vtrans_f16_kernel(
    const float* __restrict__ V, __half* __restrict__ Vt)
{
    __shared__ float t[32][33];
    const int s0 = blockIdx.x * 32, d0 = blockIdx.y * 32, bh = blockIdx.z;
    const int b = bh >> 4, h = bh & 15;
    const int tx = threadIdx.x & 31, ty = threadIdx.x >> 5;
    #pragma unroll
    for (int j = 0; j < 4; j++) {
        int s = s0 + ty + j*8;
        t[ty + j*8][tx] = V[((size_t)(b*SEQ + s))*D_MODEL + h*DK + d0 + tx];
    }
    __syncthreads();
    #pragma unroll
    for (int j = 0; j < 4; j++) {
        int d = d0 + ty + j*8;
        size_t idx = ((size_t)bh*DK + d)*SEQ + s0 + tx;
        Vt[idx] = __float2half_rn(t[tx][ty + j*8]);
    }
}

/* ================= fp16 HMMA causal flash attention =================
   smem: Q 32KB | 2 x stage { K 16KB | V 16KB } = 96KB */
#define ATTN_SMEM  (96*1024)

__global__ __launch_bounds__(256, 1) void attn_hmma_kernel(
    const __half* __restrict__ Qf, const __half* __restrict__ Kf,
    const __half* __restrict__ Vt, __half* __restrict__ Of)
{
    extern __shared__ char smem[];
    const uint32_t sb = smem_u32(smem);
    const uint32_t sQ = sb;
    const int qb = (int)gridDim.x - 1 - (int)blockIdx.x;
    const int bh = blockIdx.y;
    const int b = bh >> 4, h = bh & 15;
    const int tid = threadIdx.x, wid = tid >> 5, lane = tid & 31;
    const int r0 = lane >> 2, qd = lane & 3, lrow = lane & 15, lu = lane >> 4;

    const size_t qrow0 = (size_t)b*SEQ + (size_t)qb*128;
    const size_t krow0 = (size_t)b*SEQ;
    const int hoff = h*DK;
    const size_t vbase = (size_t)bh*DK*SEQ;
    const int NKB = 2*qb + 2;

    /* Q tile: 128 rows x 256B */
    #pragma unroll
    for (int it = 0; it < 8; it++) {
        int lin = it*256 + tid;
        int r = lin >> 4, un = lin & 15;
        uint32_t dsw = r*256 + ((un>>3)<<7) + (((un&7) ^ (r&7)) << 4);
        const void* g = Qf + (qrow0 + r)*D_MODEL + hoff + un*8;
        asm volatile("cp.async.cg.shared.global [%0], [%1], 16;" :: "r"(sQ+dsw), "l"(g));
    }

    #define LOAD_KV(kb_, s_) do {                                                  \
        uint32_t _st = sb + 32768 + (uint32_t)(s_)*32768;                          \
        size_t _kr = krow0 + (size_t)(kb_)*64;                                     \
        _Pragma("unroll")                                                          \
        for (int _it = 0; _it < 4; _it++) {                                        \
            int _lin = _it*256 + tid;                                              \
            int _r = _lin >> 4, _un = _lin & 15;                                   \
            uint32_t _d = _r*256 + ((_un>>3)<<7) + (((_un&7) ^ (_r&7)) << 4);      \
            const void* _g = Kf + (_kr + _r)*D_MODEL + hoff + _un*8;               \
            asm volatile("cp.async.cg.shared.global [%0], [%1], 16;"               \
                         :: "r"(_st+_d), "l"(_g));                                 \
        }                                                                          \
        _Pragma("unroll")                                                          \
        for (int _it = 0; _it < 4; _it++) {                                        \
            int _lin = _it*256 + tid;                                              \
            int _r = _lin >> 3, _u = _lin & 7;                                     \
            uint32_t _d = _r*128 + ((_u ^ (_r&7)) << 4);                           \
            const void* _g = Vt + vbase + (size_t)_r*SEQ + (size_t)(kb_)*64 + _u*8; \
            asm volatile("cp.async.cg.shared.global [%0], [%1], 16;"               \
                         :: "r"(_st+16384+_d), "l"(_g));                           \
        }                                                                          \
        asm volatile("cp.async.commit_group;" ::: "memory");                       \
    } while (0)

    LOAD_KV(0, 0);
    LOAD_KV(1, 1);

    float m0 = -1e30f, m1 = -1e30f, l0 = 0.f, l1 = 0.f;
    float oacc[16][4];
    #pragma unroll
    for (int i = 0; i < 16; i++)
        #pragma unroll
        for (int c = 0; c < 4; c++) oacc[i][c] = 0.f;

    for (int kb = 0; kb < NKB; kb++) {
        if (kb + 1 < NKB) asm volatile("cp.async.wait_group 1;" ::: "memory");
        else              asm volatile("cp.async.wait_group 0;" ::: "memory");
        __syncthreads();
        const uint32_t st = sb + 32768 + (uint32_t)(kb & 1)*32768;

        float sacc[8][4];
        #pragma unroll
        for (int i = 0; i < 8; i++)
            #pragma unroll
            for (int c = 0; c < 4; c++) sacc[i][c] = 0.f;

        #pragma unroll
        for (int kk = 0; kk < 8; kk++) {
            const int un = kk*2 + lu;
            const int arow = wid*16 + lrow;
            const uint32_t aoff = arow*256 + ((un>>3)<<7) + (((un&7) ^ (arow&7)) << 4);
            uint32_t a0,a1,a2,a3;
            LDSM_X4(a0,a1,a2,a3, sQ + aoff);
            #pragma unroll
            for (int nf2 = 0; nf2 < 4; nf2++) {
                const int brow = nf2*16 + lrow;
                const uint32_t boff = brow*256 + ((un>>3)<<7) + (((un&7) ^ (brow&7)) << 4);
                uint32_t b0,b1,b2,b3;
                LDSM_X4(b0,b1,b2,b3, st + boff);
                MMAF16(sacc[nf2*2+0], a0,a1,a2,a3, b0, b2);
                MMAF16(sacc[nf2*2+1], a0,a1,a2,a3, b1, b3);
            }
        }

        if (kb >= 2*qb) {
            const int rg0 = qb*128 + wid*16 + r0;
            #pragma unroll
            for (int nf = 0; nf < 8; nf++) {
                const int cg = kb*64 + nf*8 + qd*2;
                if (cg     > rg0)     sacc[nf][0] = -1e30f;
                if (cg + 1 > rg0)     sacc[nf][1] = -1e30f;
                if (cg     > rg0 + 8) sacc[nf][2] = -1e30f;
                if (cg + 1 > rg0 + 8) sacc[nf][3] = -1e30f;
            }
        }

        float mx0 = -1e30f, mx1 = -1e30f;
        #pragma unroll
        for (int nf = 0; nf < 8; nf++) {
            mx0 = fmaxf(mx0, fmaxf(sacc[nf][0], sacc[nf][1]));
            mx1 = fmaxf(mx1, fmaxf(sacc[nf][2], sacc[nf][3]));
        }
        mx0 = fmaxf(mx0, __shfl_xor_sync(0xffffffffu, mx0, 1));
        mx0 = fmaxf(mx0, __shfl_xor_sync(0xffffffffu, mx0, 2));
        mx1 = fmaxf(mx1, __shfl_xor_sync(0xffffffffu, mx1, 1));
        mx1 = fmaxf(mx1, __shfl_xor_sync(0xffffffffu, mx1, 2));
        const float mn0 = fmaxf(m0, mx0), mn1 = fmaxf(m1, mx1);
        const float c0 = exp2f(m0 - mn0), c1 = exp2f(m1 - mn1);
        float s0 = 0.f, s1 = 0.f;
        #pragma unroll
        for (int nf = 0; nf < 8; nf++) {
            sacc[nf][0] = exp2f(sacc[nf][0] - mn0); s0 += sacc[nf][0];
            sacc[nf][1] = exp2f(sacc[nf][1] - mn0); s0 += sacc[nf][1];
            sacc[nf][2] = exp2f(sacc[nf][2] - mn1); s1 += sacc[nf][2];
            sacc[nf][3] = exp2f(sacc[nf][3] - mn1); s1 += sacc[nf][3];
        }
        s0 += __shfl_xor_sync(0xffffffffu, s0, 1);
        s0 += __shfl_xor_sync(0xffffffffu, s0, 2);
        s1 += __shfl_xor_sync(0xffffffffu, s1, 1);
        s1 += __shfl_xor_sync(0xffffffffu, s1, 2);
        l0 = l0*c0 + s0; l1 = l1*c1 + s1; m0 = mn0; m1 = mn1;
        #pragma unroll
        for (int nf = 0; nf < 16; nf++) {
            oacc[nf][0] *= c0; oacc[nf][1] *= c0;
            oacc[nf][2] *= c1; oacc[nf][3] *= c1;
        }

        #pragma unroll
        for (int ks = 0; ks < 4; ks++) {
            uint32_t pa0 = pack_h2(sacc[2*ks][0],   sacc[2*ks][1]);
            uint32_t pa1 = pack_h2(sacc[2*ks][2],   sacc[2*ks][3]);
            uint32_t pa2 = pack_h2(sacc[2*ks+1][0], sacc[2*ks+1][1]);
            uint32_t pa3 = pack_h2(sacc[2*ks+1][2], sacc[2*ks+1][3]);
            const int un = ks*2 + lu;
            #pragma unroll
            for (int nf2 = 0; nf2 < 8; nf2++) {
                const int vrow = nf2*16 + lrow;
                const uint32_t voff = vrow*128 + ((un ^ (vrow&7)) << 4);
                uint32_t v0,v1,v2,v3;
                LDSM_X4(v0,v1,v2,v3, st + 16384 + voff);
                MMAF16(oacc[nf2*2+0], pa0,pa1,pa2,pa3, v0, v2);
                MMAF16(oacc[nf2*2+1], pa0,pa1,pa2,pa3, v1, v3);
            }
        }
        __syncthreads();
        if (kb + 2 < NKB) LOAD_KV(kb + 2, kb & 1);
    }

    const float inv0 = 1.f / l0, inv1 = 1.f / l1;
    const size_t row0 = qrow0 + wid*16 + r0;
    #pragma unroll
    for (int nf = 0; nf < 16; nf++) {
        const size_t c = (size_t)hoff + nf*8 + qd*2;
        h16_store2(Of, row0*D_MODEL + c,
                   oacc[nf][0]*inv0, oacc[nf][1]*inv0);
        h16_store2(Of, (row0+8)*D_MODEL + c,
                   oacc[nf][2]*inv1, oacc[nf][3]*inv1);
    }
    #undef LOAD_KV
}

/* ================= launch ================= */
extern "C" void kernel_launch(void* const* d_in, const int* in_sizes, int n_in,
                              void* d_out, int out_size)
{
    const float* x  = (const float*)d_in[0];
    const float* Wq = (const float*)d_in[1];
    const float* Wk = (const float*)d_in[2];
    const float* Wv = (const float*)d_in[3];
    const float* Wo = (const float*)d_in[4];
    const float* W1 = (const float*)d_in[5];
    const float* W2 = (const float*)d_in[6];
    const float* W3 = (const float*)d_in[7];
    const float* g1 = (const float*)d_in[8];
    const float* g2 = (const float*)d_in[9];
    float* out = (float*)d_out;

    float *v, *res;
    cudaGetSymbolAddress((void**)&v,   g_v);
    cudaGetSymbolAddress((void**)&res, g_res);

    __half *xnf, *atf, *f1f, *qf, *kf, *vtf, *wqkv, *wo, *w13, *w2;
    cudaGetSymbolAddress((void**)&xnf, g_xnf);
    cudaGetSymbolAddress((void**)&atf, g_atf);
    cudaGetSymbolAddress((void**)&f1f, g_f1f);
    cudaGetSymbolAddress((void**)&qf,  g_qf);
    cudaGetSymbolAddress((void**)&kf,  g_kf);
    cudaGetSymbolAddress((void**)&vtf, g_vtf);
    cudaGetSymbolAddress((void**)&wqkv, g_wqkv);
    cudaGetSymbolAddress((void**)&wo,  g_wo);
    cudaGetSymbolAddress((void**)&w13, g_w13);
    cudaGetSymbolAddress((void**)&w2,  g_w2);

    cudaFuncSetAttribute(gemm16_kernel<0>,
        cudaFuncAttributeMaxDynamicSharedMemorySize, F_SMEM);
    cudaFuncSetAttribute(gemm16_kernel<1>,
        cudaFuncAttributeMaxDynamicSharedMemorySize, F_SMEM);
    cudaFuncSetAttribute(gemm16_kernel<2>,
        cudaFuncAttributeMaxDynamicSharedMemorySize, F_SMEM);
    cudaFuncSetAttribute(attn_hmma_kernel,
        cudaFuncAttributeMaxDynamicSharedMemorySize, ATTN_SMEM);

    /* 0. all weight conversions in one launch */
    {
        size_t total4 = 4*((size_t)D_MODEL*D_MODEL/4) + 3*((size_t)D_FF*D_MODEL/4);
        megasplit_kernel<<<(unsigned)((total4 + 255)/256), 256>>>(
            Wq, Wk, Wv, Wo, W1, W3, W2, wqkv, wo, w13, w2);
    }

    /* 1. xn = rmsnorm(x, g1) -> fp16 */
    rmsnorm_f16_kernel<<<ROWS, 256>>>(x, g1, xnf);

    /* 2. merged QKV projection; q/k roped fp16, v fp32 */
    gemm16_kernel<1><<<dim3(48, ROWS/256), 256, F_SMEM>>>(
        xnf, wqkv, v, nullptr, qf, kf, ROWS, D_MODEL, D_MODEL);

    /* 3. V transpose -> fp16 */
    vtrans_f16_kernel<<<dim3(SEQ/32, DK/32, BATCH*NH), 256>>>(v, vtf);

    /* 4. attention (fp16) */
    attn_hmma_kernel<<<dim3(SEQ/128, BATCH*NH), 256, ATTN_SMEM>>>(
        qf, kf, vtf, atf);

    /* 5. res = x + att @ Wo^T */
    gemm16_kernel<0><<<dim3(16, ROWS/256), 256, F_SMEM>>>(
        atf, wo, res, x, nullptr, nullptr, ROWS, D_MODEL, D_MODEL);

    /* 6. xn2 = rmsnorm(res, g2) -> fp16 */
    rmsnorm_f16_kernel<<<ROWS, 256>>>(res, g2, xnf);

    /* 7. merged W13 GEMM + fused swiglu -> fp16 h */
    gemm16_kernel<2><<<dim3(86, ROWS/256), 256, F_SMEM>>>(
        xnf, w13, nullptr, nullptr, f1f, nullptr, ROWS, D_FF, D_MODEL);

    /* 8. out = res + h @ W2^T */
    gemm16_kernel<0><<<dim3(16, ROWS/256), 256, F_SMEM>>>(
        f1f, w2, out, res, nullptr, nullptr, ROWS, D_MODEL, D_FF);
}

// round 17
// speedup vs baseline: 2.6025x; 1.0371x over previous
#include <cuda_runtime.h>
#include <cuda_bf16.h>
#include <cuda_fp16.h>
#include <math.h>
#include <stdint.h>

#define D_MODEL 2048
#define SEQ     2048
#define BATCH   2
#define ROWS    (BATCH*SEQ)     /* 4096 */
#define D_FF    5504
#define NH      16
#define DK      128

/* ================= scratch ================= */
__device__ float g_res[(size_t)ROWS*D_MODEL];

__device__ __half g_xnf[(size_t)ROWS*D_MODEL];   /* fp16 activations */
__device__ __half g_atf[(size_t)ROWS*D_MODEL];   /* attention out */
__device__ __half g_f1f[(size_t)ROWS*D_FF];      /* swiglu out */
__device__ __half g_qf [(size_t)ROWS*D_MODEL];   /* q (roped, scaled) */
__device__ __half g_kf [(size_t)ROWS*D_MODEL];   /* k (roped) */
__device__ __half g_vtf[(size_t)BATCH*NH*DK*SEQ];/* v transposed */

__device__ __half g_wqkv[(size_t)3*D_MODEL*D_MODEL];
__device__ __half g_wo  [(size_t)D_MODEL*D_MODEL];
__device__ __half g_w13 [(size_t)2*D_FF*D_MODEL];
__device__ __half g_w2  [(size_t)D_MODEL*D_FF];

/* ================= helpers ================= */
__device__ __forceinline__ uint32_t smem_u32(const void* p) {
    uint32_t a;
    asm("{ .reg .u64 t; cvta.to.shared.u64 t, %1; cvt.u32.u64 %0, t; }"
        : "=r"(a) : "l"(p));
    return a;
}

#define LDSM_X4(r0,r1,r2,r3, addr) \
    asm volatile("ldmatrix.sync.aligned.m8n8.x4.shared.b16 {%0,%1,%2,%3}, [%4];" \
        : "=r"(r0),"=r"(r1),"=r"(r2),"=r"(r3) : "r"(addr))

#define MMAF16(d, a0,a1,a2,a3, b0,b1) \
    asm volatile("mma.sync.aligned.m16n8k16.row.col.f32.f16.f16.f32 " \
        "{%0,%1,%2,%3}, {%4,%5,%6,%7}, {%8,%9}, {%0,%1,%2,%3};" \
        : "+f"((d)[0]),"+f"((d)[1]),"+f"((d)[2]),"+f"((d)[3]) \
        : "r"(a0),"r"(a1),"r"(a2),"r"(a3), "r"(b0),"r"(b1))

__device__ __forceinline__ void h16_store2(__half* W, size_t idx, float x, float y) {
    *reinterpret_cast<__half2*>(W + idx) =
        __half2(__float2half_rn(x), __float2half_rn(y));
}

__device__ __forceinline__ uint32_t pack_h2(float x, float y) {
    __half2 h(__float2half_rn(x), __float2half_rn(y));
    return *reinterpret_cast<uint32_t*>(&h);
}

/* ================= prep: rmsnorm1 + all weight converts in ONE launch ====
   blocks [0, ROWS): rmsnorm(x,g1)->xnf ; blocks [ROWS, ...): weight quads */
__global__ __launch_bounds__(256) void prep_kernel(
    const float* __restrict__ X, const float* __restrict__ g,
    __half* __restrict__ Y,
    const float* __restrict__ Wq, const float* __restrict__ Wk,
    const float* __restrict__ Wv, const float* __restrict__ Wo,
    const float* __restrict__ W1, const float* __restrict__ W3,
    const float* __restrict__ W2,
    __half* qkvF, __half* woF, __half* w13F, __half* w2F)
{
    if (blockIdx.x < ROWS) {
        const int row = blockIdx.x;
        const float* x = X + (size_t)row * D_MODEL;
        float ss = 0.f;
        #pragma unroll
        for (int i = threadIdx.x; i < D_MODEL/4; i += 256) {
            float4 v = ((const float4*)x)[i];
            ss += v.x*v.x + v.y*v.y + v.z*v.z + v.w*v.w;
        }
        #pragma unroll
        for (int off = 16; off; off >>= 1)
            ss += __shfl_xor_sync(0xffffffffu, ss, off);
        __shared__ float red[8];
        if ((threadIdx.x & 31) == 0) red[threadIdx.x >> 5] = ss;
        __syncthreads();
        float tot = red[0]+red[1]+red[2]+red[3]+red[4]+red[5]+red[6]+red[7];
        float rinv = rsqrtf(tot * (1.0f / D_MODEL) + 1e-5f);
        #pragma unroll
        for (int i = threadIdx.x; i < D_MODEL/4; i += 256) {
            float4 v = ((const float4*)x)[i];
            float4 gg = ((const float4*)g)[i];
            size_t base = (size_t)row * D_MODEL + i*4;
            h16_store2(Y, base,   v.x*rinv*gg.x, v.y*rinv*gg.y);
            h16_store2(Y, base+2, v.z*rinv*gg.z, v.w*rinv*gg.w);
        }
        return;
    }

    const size_t S1 = (size_t)D_MODEL*D_MODEL/4;
    const size_t S2 = (size_t)D_FF*D_MODEL/4;
    size_t i4 = (size_t)(blockIdx.x - ROWS)*256 + threadIdx.x;
    if (i4 >= 4*S1 + 3*S2) return;

    float4 v; __half* F; size_t d4;
    if (i4 < 3*S1) {
        size_t seg = i4 / S1, off = i4 - seg*S1;
        const float* W = (seg == 0) ? Wq : (seg == 1) ? Wk : Wv;
        v = ((const float4*)W)[off];
        F = qkvF; d4 = i4;
    } else if (i4 < 4*S1) {
        size_t off = i4 - 3*S1;
        v = ((const float4*)Wo)[off];
        F = woF; d4 = off;
    } else if (i4 < 4*S1 + 2*S2) {
        size_t off = i4 - 4*S1;
        int isW3 = off >= S2; if (isW3) off -= S2;
        v = ((const float4*)(isW3 ? W3 : W1))[off];
        size_t r = off >> 9, c = off & 511;
        size_t d = (r >> 6)*128 + (isW3 ? 64 : 0) + (r & 63);
        F = w13F; d4 = d*512 + c;
    } else {
        size_t off = i4 - 4*S1 - 2*S2;
        v = ((const float4*)W2)[off];
        F = w2F; d4 = off;
    }
    h16_store2(F, d4*4,   v.x, v.y);
    h16_store2(F, d4*4+2, v.z, v.w);
}

/* ================= RMSNorm -> fp16 (standalone, for step 6) ============ */
__global__ __launch_bounds__(256) void rmsnorm_f16_kernel(
    const float* __restrict__ X, const float* __restrict__ g,
    __half* __restrict__ Y)
{
    const int row = blockIdx.x;
    const float* x = X + (size_t)row * D_MODEL;

    float ss = 0.f;
    #pragma unroll
    for (int i = threadIdx.x; i < D_MODEL/4; i += 256) {
        float4 v = ((const float4*)x)[i];
        ss += v.x*v.x + v.y*v.y + v.z*v.z + v.w*v.w;
    }
    #pragma unroll
    for (int off = 16; off; off >>= 1)
        ss += __shfl_xor_sync(0xffffffffu, ss, off);
    __shared__ float red[8];
    if ((threadIdx.x & 31) == 0) red[threadIdx.x >> 5] = ss;
    __syncthreads();
    float tot = red[0]+red[1]+red[2]+red[3]+red[4]+red[5]+red[6]+red[7];
    float rinv = rsqrtf(tot * (1.0f / D_MODEL) + 1e-5f);

    #pragma unroll
    for (int i = threadIdx.x; i < D_MODEL/4; i += 256) {
        float4 v = ((const float4*)x)[i];
        float4 gg = ((const float4*)g)[i];
        size_t base = (size_t)row * D_MODEL + i*4;
        h16_store2(Y, base,   v.x*rinv*gg.x, v.y*rinv*gg.y);
        h16_store2(Y, base+2, v.z*rinv*gg.z, v.w*rinv*gg.w);
    }
}

/* ================= fp16 HMMA GEMM, 256x128 tile, 4-stage =======
   MODE 0: C = A B^T + R (fp32 out)
   MODE 1: QKV merged; q (RoPE*QSC) -> OF, k (RoPE) -> OF2,
           v -> VT fp16 TRANSPOSED [bh][d][s] via smem staging
   MODE 2: W13 merged; h = silu(f1)*f3 -> OF */
#define F_STAGE   49152                     /* A 32KB + B 16KB */
#define F_GSTAGES 4
#define F_SMEM    (F_GSTAGES*F_STAGE)       /* 192KB */

template<int MODE>
__global__ __launch_bounds__(256, 1) void gemm16_kernel(
    const __half* __restrict__ A, const __half* __restrict__ B,
    float* __restrict__ C, const float* __restrict__ R,
    __half* __restrict__ OF, __half* __restrict__ OF2,
    __half* __restrict__ VT,
    int M, int N, int K)
{
    extern __shared__ char smem[];
    const uint32_t sb = smem_u32(smem);
    const int tid = threadIdx.x;
    const int wid = tid >> 5, lane = tid & 31;
    const int wr = wid & 3;
    const int wc = wid >> 2;
    const int NC = K / 64;

    const int rowA = blockIdx.y * 256;
    const int rowB = blockIdx.x * 128;

    const __half* srcA = A + (size_t)rowA * K;
    const __half* srcB = B + (size_t)rowB * K;

    const int r0 = tid >> 3;
    const int u  = tid & 7;

    #define LOAD_STAGE16(chunk, s) do {                                      \
        uint32_t _stb = sb + (s) * F_STAGE;                                  \
        size_t _k0 = (size_t)(chunk) * 64;                                   \
        _Pragma("unroll")                                                    \
        for (int _i = 0; _i < 8; _i++) {                                     \
            int _r = r0 + _i * 32;                                           \
            uint32_t _d = _r * 128 + ((u ^ (_r & 7)) * 16);                  \
            const void* _g = srcA + (size_t)_r * K + _k0 + u * 8;            \
            asm volatile("cp.async.cg.shared.global [%0], [%1], 16;"         \
                         :: "r"(_stb + _d), "l"(_g));                        \
        }                                                                    \
        _Pragma("unroll")                                                    \
        for (int _i = 0; _i < 4; _i++) {                                     \
            int _r = r0 + _i * 32;                                           \
            uint32_t _d = _r * 128 + ((u ^ (_r & 7)) * 16);                  \
            const void* _g = srcB + (size_t)_r * K + _k0 + u * 8;            \
            asm volatile("cp.async.cg.shared.global [%0], [%1], 16;"         \
                         :: "r"(_stb + 32768 + _d), "l"(_g));                \
        }                                                                    \
        asm volatile("cp.async.commit_group;" ::: "memory");                 \
    } while (0)

    LOAD_STAGE16(0, 0);
    if (NC > 1) LOAD_STAGE16(1, 1);
    if (NC > 2) LOAD_STAGE16(2, 2);
    if (NC > 3) LOAD_STAGE16(3, 3);

    float acc[4][8][4];
    #pragma unroll
    for (int i = 0; i < 4; i++)
        #pragma unroll
        for (int j = 0; j < 8; j++)
            #pragma unroll
            for (int c = 0; c < 4; c++) acc[i][j][c] = 0.f;

    const int lrow = lane & 15;
    const int lu   = lane >> 4;

    for (int j = 0; j < NC; j++) {
        {
            int pend = NC - 1 - j; if (pend > 3) pend = 3;
            if (pend == 3)      asm volatile("cp.async.wait_group 3;" ::: "memory");
            else if (pend == 2) asm volatile("cp.async.wait_group 2;" ::: "memory");
            else if (pend == 1) asm volatile("cp.async.wait_group 1;" ::: "memory");
            else                asm volatile("cp.async.wait_group 0;" ::: "memory");
        }
        __syncthreads();

        const uint32_t stb = sb + (j % F_GSTAGES) * F_STAGE;
        const uint32_t tA = stb;
        const uint32_t tB = stb + 32768;

        #pragma unroll
        for (int ks = 0; ks < 4; ks++) {
            const int unit = ks*2 + lu;
            uint32_t a[4][4];
            #pragma unroll
            for (int mf = 0; mf < 4; mf++) {
                const int row = wr*64 + mf*16 + lrow;
                const uint32_t off = row*128 + ((unit ^ (row & 7)) << 4);
                LDSM_X4(a[mf][0], a[mf][1], a[mf][2], a[mf][3], tA + off);
            }
            #pragma unroll
            for (int nf2 = 0; nf2 < 4; nf2++) {
                const int brow = wc*64 + nf2*16 + lrow;
                const uint32_t off = brow*128 + ((unit ^ (brow & 7)) << 4);
                uint32_t b0,b1,b2,b3;
                LDSM_X4(b0,b1,b2,b3, tB + off);
                #pragma unroll
                for (int mf = 0; mf < 4; mf++) {
                    MMAF16(acc[mf][nf2*2+0], a[mf][0],a[mf][1],a[mf][2],a[mf][3], b0, b2);
                    MMAF16(acc[mf][nf2*2+1], a[mf][0],a[mf][1],a[mf][2],a[mf][3], b1, b3);
                }
            }
        }
        __syncthreads();
        if (j + F_GSTAGES < NC) LOAD_STAGE16(j + F_GSTAGES, j % F_GSTAGES);
    }

    const int erowL = wr*64 + (lane >> 2);
    const int ecolL = wc*64 + (lane & 3)*2;

    if (MODE == 0) {
        const int erow = rowA + erowL;
        const int ecol = rowB + ecolL;
        #pragma unroll
        for (int mf = 0; mf < 4; mf++) {
            #pragma unroll
            for (int half = 0; half < 2; half++) {
                const int row = erow + mf*16 + half*8;
                float* crow = C + (size_t)row * N + ecol;
                const float* rrow = R + (size_t)row * N + ecol;
                #pragma unroll
                for (int nf = 0; nf < 8; nf++) {
                    float2 v = make_float2(acc[mf][nf][half*2+0], acc[mf][nf][half*2+1]);
                    float2 rv = *(const float2*)(rrow + nf*8);
                    v.x += rv.x; v.y += rv.y;
                    *(float2*)(crow + nf*8) = v;
                }
            }
        }
    } else if (MODE == 1) {
        const int seg = blockIdx.x >> 4;
        const int colT0 = ((blockIdx.x & 15) << 7) + ecolL;
        if (seg == 2) {
            /* v: stage transposed through smem, emit fp16 [bh][d][s] */
            __half* smt = (__half*)smem;       /* [128][264] pad */
            __syncthreads();
            #pragma unroll
            for (int mf = 0; mf < 4; mf++) {
                #pragma unroll
                for (int half = 0; half < 2; half++) {
                    const int sl = erowL + mf*16 + half*8;  /* 0..255 */
                    #pragma unroll
                    for (int nf = 0; nf < 8; nf++) {
                        const int d = ecolL + nf*8;          /* local d */
                        smt[(d  )*264 + sl] = __float2half_rn(acc[mf][nf][half*2+0]);
                        smt[(d+1)*264 + sl] = __float2half_rn(acc[mf][nf][half*2+1]);
                    }
                }
            }
            __syncthreads();
            const int h = blockIdx.x & 15;
            const int b = rowA >> 11;
            const int s0b = rowA & (SEQ-1);
            __half* vdst = VT + ((size_t)(b*NH + h)*DK)*SEQ + s0b;
            #pragma unroll
            for (int it = 0; it < 16; it++) {
                int lin = it*256 + tid;
                int d = lin >> 5, uu = lin & 31;
                uint4 val = *(const uint4*)(smt + d*264 + uu*8);
                *(uint4*)(vdst + (size_t)d*SEQ + uu*8) = val;
            }
        } else {
            const float QSC = 0.08838834764831845f * 1.4426950408889634f;
            #pragma unroll
            for (int mf = 0; mf < 4; mf++) {
                #pragma unroll
                for (int half = 0; half < 2; half++) {
                    const int rowg = rowA + erowL + mf*16 + half*8;
                    const int s = rowg & (SEQ-1);
                    #pragma unroll
                    for (int nf = 0; nf < 8; nf++) {
                        const int col = colT0 + nf*8;
                        float v0 = acc[mf][nf][half*2+0];
                        float v1 = acc[mf][nf][half*2+1];
                        const int kidx = (col & 127) >> 1;
                        const float freq = expf(-0.14391156831212824f * (float)kidx);
                        float sn, cs;
                        sincosf((float)s * freq, &sn, &cs);
                        float e = v0*cs - v1*sn;
                        float o = v0*sn + v1*cs;
                        if (seg == 0) {
                            h16_store2(OF, (size_t)rowg*D_MODEL + col, e*QSC, o*QSC);
                        } else {
                            h16_store2(OF2, (size_t)rowg*D_MODEL + col, e, o);
                        }
                    }
                }
            }
        }
    } else {
        /* MODE 2: wc=0 f1, wc=1 f3 of same global cols; exchange via smem */
        float* sx = (float*)smem;
        __syncthreads();
        if (wc == 1) {
            #pragma unroll
            for (int mf = 0; mf < 4; mf++) {
                #pragma unroll
                for (int half = 0; half < 2; half++) {
                    const int rl = erowL + mf*16 + half*8;
                    #pragma unroll
                    for (int nf = 0; nf < 8; nf++) {
                        const int jj = (ecolL - 64) + nf*8;
                        sx[rl*68 + jj]     = acc[mf][nf][half*2+0];
                        sx[rl*68 + jj + 1] = acc[mf][nf][half*2+1];
                    }
                }
            }
        }
        __syncthreads();
        if (wc == 0) {
            #pragma unroll
            for (int mf = 0; mf < 4; mf++) {
                #pragma unroll
                for (int half = 0; half < 2; half++) {
                    const int rl = erowL + mf*16 + half*8;
                    const size_t rowg = (size_t)(rowA + rl);
                    #pragma unroll
                    for (int nf = 0; nf < 8; nf++) {
                        const int jj = ecolL + nf*8;
                        float a0 = acc[mf][nf][half*2+0];
                        float a1 = acc[mf][nf][half*2+1];
                        float b0 = sx[rl*68 + jj];
                        float b1 = sx[rl*68 + jj + 1];
                        float h0 = a0 / (1.f + expf(-a0)) * b0;
                        float h1 = a1 / (1.f + expf(-a1)) * b1;
                        h16_store2(OF, rowg*D_FF + (size_t)blockIdx.x*64 + jj,
                                   h0, h1);
                    }
                }
            }
        }
    }
    #undef LOAD_STAGE16
}

/* ================= fp16 HMMA causal flash attention =================
   smem: Q 32KB | 2 x stage { K 16KB | V 16KB } = 96KB */
#define ATTN_SMEM  (96*1024)

__global__ __launch_bounds__(256, 1) void attn_hmma_kernel(
    const __half* __restrict__ Qf, const __half* __restrict__ Kf,
    const __half* __restrict__ Vt, __half* __restrict__ Of)
{
    extern __shared__ char smem[];
    const uint32_t sb = smem_u32(smem);
    const uint32_t sQ = sb;
    const int qb = (int)gridDim.x - 1 - (int)blockIdx.x;
    const int bh = blockIdx.y;
    const int b = bh >> 4, h = bh & 15;
    const int tid = threadIdx.x, wid = tid >> 5, lane = tid & 31;
    const int r0 = lane >> 2, qd = lane & 3, lrow = lane & 15, lu = lane >> 4;

    const size_t qrow0 = (size_t)b*SEQ + (size_t)qb*128;
    const size_t krow0 = (size_t)b*SEQ;
    const int hoff = h*DK;
    const size_t vbase = (size_t)bh*DK*SEQ;
    const int NKB = 2*qb + 2;

    #pragma unroll
    for (int it = 0; it < 8; it++) {
        int lin = it*256 + tid;
        int r = lin >> 4, un = lin & 15;
        uint32_t dsw = r*256 + ((un>>3)<<7) + (((un&7) ^ (r&7)) << 4);
        const void* g = Qf + (qrow0 + r)*D_MODEL + hoff + un*8;
        asm volatile("cp.async.cg.shared.global [%0], [%1], 16;" :: "r"(sQ+dsw), "l"(g));
    }

    #define LOAD_KV(kb_, s_) do {                                                  \
        uint32_t _st = sb + 32768 + (uint32_t)(s_)*32768;                          \
        size_t _kr = krow0 + (size_t)(kb_)*64;                                     \
        _Pragma("unroll")                                                          \
        for (int _it = 0; _it < 4; _it++) {                                        \
            int _lin = _it*256 + tid;                                              \
            int _r = _lin >> 4, _un = _lin & 15;                                   \
            uint32_t _d = _r*256 + ((_un>>3)<<7) + (((_un&7) ^ (_r&7)) << 4);      \
            const void* _g = Kf + (_kr + _r)*D_MODEL + hoff + _un*8;               \
            asm volatile("cp.async.cg.shared.global [%0], [%1], 16;"               \
                         :: "r"(_st+_d), "l"(_g));                                 \
        }                                                                          \
        _Pragma("unroll")                                                          \
        for (int _it = 0; _it < 4; _it++) {                                        \
            int _lin = _it*256 + tid;                                              \
            int _r = _lin >> 3, _u = _lin & 7;                                     \
            uint32_t _d = _r*128 + ((_u ^ (_r&7)) << 4);                           \
            const void* _g = Vt + vbase + (size_t)_r*SEQ + (size_t)(kb_)*64 + _u*8; \
            asm volatile("cp.async.cg.shared.global [%0], [%1], 16;"               \
                         :: "r"(_st+16384+_d), "l"(_g));                           \
        }                                                                          \
        asm volatile("cp.async.commit_group;" ::: "memory");                       \
    } while (0)

    LOAD_KV(0, 0);
    LOAD_KV(1, 1);

    float m0 = -1e30f, m1 = -1e30f, l0 = 0.f, l1 = 0.f;
    float oacc[16][4];
    #pragma unroll
    for (int i = 0; i < 16; i++)
        #pragma unroll
        for (int c = 0; c < 4; c++) oacc[i][c] = 0.f;

    for (int kb = 0; kb < NKB; kb++) {
        if (kb + 1 < NKB) asm volatile("cp.async.wait_group 1;" ::: "memory");
        else              asm volatile("cp.async.wait_group 0;" ::: "memory");
        __syncthreads();
        const uint32_t st = sb + 32768 + (uint32_t)(kb & 1)*32768;

        float sacc[8][4];
        #pragma unroll
        for (int i = 0; i < 8; i++)
            #pragma unroll
            for (int c = 0; c < 4; c++) sacc[i][c] = 0.f;

        #pragma unroll
        for (int kk = 0; kk < 8; kk++) {
            const int un = kk*2 + lu;
            const int arow = wid*16 + lrow;
            const uint32_t aoff = arow*256 + ((un>>3)<<7) + (((un&7) ^ (arow&7)) << 4);
            uint32_t a0,a1,a2,a3;
            LDSM_X4(a0,a1,a2,a3, sQ + aoff);
            #pragma unroll
            for (int nf2 = 0; nf2 < 4; nf2++) {
                const int brow = nf2*16 + lrow;
                const uint32_t boff = brow*256 + ((un>>3)<<7) + (((un&7) ^ (brow&7)) << 4);
                uint32_t b0,b1,b2,b3;
                LDSM_X4(b0,b1,b2,b3, st + boff);
                MMAF16(sacc[nf2*2+0], a0,a1,a2,a3, b0, b2);
                MMAF16(sacc[nf2*2+1], a0,a1,a2,a3, b1, b3);
            }
        }

        if (kb >= 2*qb) {
            const int rg0 = qb*128 + wid*16 + r0;
            #pragma unroll
            for (int nf = 0; nf < 8; nf++) {
                const int cg = kb*64 + nf*8 + qd*2;
                if (cg     > rg0)     sacc[nf][0] = -1e30f;
                if (cg + 1 > rg0)     sacc[nf][1] = -1e30f;
                if (cg     > rg0 + 8) sacc[nf][2] = -1e30f;
                if (cg + 1 > rg0 + 8) sacc[nf][3] = -1e30f;
            }
        }

        float mx0 = -1e30f, mx1 = -1e30f;
        #pragma unroll
        for (int nf = 0; nf < 8; nf++) {
            mx0 = fmaxf(mx0, fmaxf(sacc[nf][0], sacc[nf][1]));
            mx1 = fmaxf(mx1, fmaxf(sacc[nf][2], sacc[nf][3]));
        }
        mx0 = fmaxf(mx0, __shfl_xor_sync(0xffffffffu, mx0, 1));
        mx0 = fmaxf(mx0, __shfl_xor_sync(0xffffffffu, mx0, 2));
        mx1 = fmaxf(mx1, __shfl_xor_sync(0xffffffffu, mx1, 1));
        mx1 = fmaxf(mx1, __shfl_xor_sync(0xffffffffu, mx1, 2));
        const float mn0 = fmaxf(m0, mx0), mn1 = fmaxf(m1, mx1);
        const float c0 = exp2f(m0 - mn0), c1 = exp2f(m1 - mn1);
        float s0 = 0.f, s1 = 0.f;
        #pragma unroll
        for (int nf = 0; nf < 8; nf++) {
            sacc[nf][0] = exp2f(sacc[nf][0] - mn0); s0 += sacc[nf][0];
            sacc[nf][1] = exp2f(sacc[nf][1] - mn0); s0 += sacc[nf][1];
            sacc[nf][2] = exp2f(sacc[nf][2] - mn1); s1 += sacc[nf][2];
            sacc[nf][3] = exp2f(sacc[nf][3] - mn1); s1 += sacc[nf][3];
        }
        s0 += __shfl_xor_sync(0xffffffffu, s0, 1);
        s0 += __shfl_xor_sync(0xffffffffu, s0, 2);
        s1 += __shfl_xor_sync(0xffffffffu, s1, 1);
        s1 += __shfl_xor_sync(0xffffffffu, s1, 2);
        l0 = l0*c0 + s0; l1 = l1*c1 + s1; m0 = mn0; m1 = mn1;
        #pragma unroll
        for (int nf = 0; nf < 16; nf++) {
            oacc[nf][0] *= c0; oacc[nf][1] *= c0;
            oacc[nf][2] *= c1; oacc[nf][3] *= c1;
        }

        #pragma unroll
        for (int ks = 0; ks < 4; ks++) {
            uint32_t pa0 = pack_h2(sacc[2*ks][0],   sacc[2*ks][1]);
            uint32_t pa1 = pack_h2(sacc[2*ks][2],   sacc[2*ks][3]);
            uint32_t pa2 = pack_h2(sacc[2*ks+1][0], sacc[2*ks+1][1]);
            uint32_t pa3 = pack_h2(sacc[2*ks+1][2], sacc[2*ks+1][3]);
            const int un = ks*2 + lu;
            #pragma unroll
            for (int nf2 = 0; nf2 < 8; nf2++) {
                const int vrow = nf2*16 + lrow;
                const uint32_t voff = vrow*128 + ((un ^ (vrow&7)) << 4);
                uint32_t v0,v1,v2,v3;
                LDSM_X4(v0,v1,v2,v3, st + 16384 + voff);
                MMAF16(oacc[nf2*2+0], pa0,pa1,pa2,pa3, v0, v2);
                MMAF16(oacc[nf2*2+1], pa0,pa1,pa2,pa3, v1, v3);
            }
        }
        __syncthreads();
        if (kb + 2 < NKB) LOAD_KV(kb + 2, kb & 1);
    }

    const float inv0 = 1.f / l0, inv1 = 1.f / l1;
    const size_t row0 = qrow0 + wid*16 + r0;
    #pragma unroll
    for (int nf = 0; nf < 16; nf++) {
        const size_t c = (size_t)hoff + nf*8 + qd*2;
        h16_store2(Of, row0*D_MODEL + c,
                   oacc[nf][0]*inv0, oacc[nf][1]*inv0);
        h16_store2(Of, (row0+8)*D_MODEL + c,
                   oacc[nf][2]*inv1, oacc[nf][3]*inv1);
    }
    #undef LOAD_KV
}

/* ================= launch ================= */
extern "C" void kernel_launch(void* const* d_in, const int* in_sizes, int n_in,
                              void* d_out, int out_size)
{
    const float* x  = (const float*)d_in[0];
    const float* Wq = (const float*)d_in[1];
    const float* Wk = (const float*)d_in[2];
    const float* Wv = (const float*)d_in[3];
    const float* Wo = (const float*)d_in[4];
    const float* W1 = (const float*)d_in[5];
    const float* W2 = (const float*)d_in[6];
    const float* W3 = (const float*)d_in[7];
    const float* g1 = (const float*)d_in[8];
    const float* g2 = (const float*)d_in[9];
    float* out = (float*)d_out;

    float *res;
    cudaGetSymbolAddress((void**)&res, g_res);

    __half *xnf, *atf, *f1f, *qf, *kf, *vtf, *wqkv, *wo, *w13, *w2;
    cudaGetSymbolAddress((void**)&xnf, g_xnf);
    cudaGetSymbolAddress((void**)&atf, g_atf);
    cudaGetSymbolAddress((void**)&f1f, g_f1f);
    cudaGetSymbolAddress((void**)&qf,  g_qf);
    cudaGetSymbolAddress((void**)&kf,  g_kf);
    cudaGetSymbolAddress((void**)&vtf, g_vtf);
    cudaGetSymbolAddress((void**)&wqkv, g_wqkv);
    cudaGetSymbolAddress((void**)&wo,  g_wo);
    cudaGetSymbolAddress((void**)&w13, g_w13);
    cudaGetSymbolAddress((void**)&w2,  g_w2);

    cudaFuncSetAttribute(gemm16_kernel<0>,
        cudaFuncAttributeMaxDynamicSharedMemorySize, F_SMEM);
    cudaFuncSetAttribute(gemm16_kernel<1>,
        cudaFuncAttributeMaxDynamicSharedMemorySize, F_SMEM);
    cudaFuncSetAttribute(gemm16_kernel<2>,
        cudaFuncAttributeMaxDynamicSharedMemorySize, F_SMEM);
    cudaFuncSetAttribute(attn_hmma_kernel,
        cudaFuncAttributeMaxDynamicSharedMemorySize, ATTN_SMEM);

    /* 0+1. rmsnorm1 + all weight conversions in ONE launch */
    {
        size_t total4 = 4*((size_t)D_MODEL*D_MODEL/4) + 3*((size_t)D_FF*D_MODEL/4);
        unsigned wblocks = (unsigned)((total4 + 255)/256);
        prep_kernel<<<ROWS + wblocks, 256>>>(
            x, g1, xnf, Wq, Wk, Wv, Wo, W1, W3, W2, wqkv, wo, w13, w2);
    }

    /* 2. merged QKV projection; q/k roped fp16, v transposed fp16 */
    gemm16_kernel<1><<<dim3(48, ROWS/256), 256, F_SMEM>>>(
        xnf, wqkv, nullptr, nullptr, qf, kf, vtf, ROWS, D_MODEL, D_MODEL);

    /* 3. attention (fp16) */
    attn_hmma_kernel<<<dim3(SEQ/128, BATCH*NH), 256, ATTN_SMEM>>>(
        qf, kf, vtf, atf);

    /* 4. res = x + att @ Wo^T */
    gemm16_kernel<0><<<dim3(16, ROWS/256), 256, F_SMEM>>>(
        atf, wo, res, x, nullptr, nullptr, nullptr, ROWS, D_MODEL, D_MODEL);

    /* 5. xn2 = rmsnorm(res, g2) -> fp16 */
    rmsnorm_f16_kernel<<<ROWS, 256>>>(res, g2, xnf);

    /* 6. merged W13 GEMM + fused swiglu -> fp16 h */
    gemm16_kernel<2><<<dim3(86, ROWS/256), 256, F_SMEM>>>(
        xnf, w13, nullptr, nullptr, f1f, nullptr, nullptr, ROWS, D_FF, D_MODEL);

    /* 7. out = res + h @ W2^T */
    gemm16_kernel<0><<<dim3(16, ROWS/256), 256, F_SMEM>>>(
        f1f, w2, out, res, nullptr, nullptr, nullptr, ROWS, D_MODEL, D_FF);
}